// round 3
// baseline (speedup 1.0000x reference)
#include <cuda_runtime.h>

#define NT  50000
#define NE  800000
#define NEG_SLOPE 0.2f
#define NB  196        // ceil(50000/256)
#define GBK 391        // ceil(50000/128) gemm row tiles
#define AB  6250       // warp-per-node blocks (8 nodes/block)
#define EB  3125       // ceil(800000/256) edge blocks

// ---------------- scratch (static device globals) ---------------------------
__device__ float g_H[4][(size_t)NT * 64];   // 0=tt_src,1=dt_src,2=dd_src,3=td_src
__device__ float g_alpha[8][NT];
__device__ float g_v[8][128];
__device__ float g_den[4][NT];
__device__ int2  g_edges[4][NE];            // {src, exp(logit) bits}
__device__ int   g_cnt[4][NT];
__device__ int   g_cur[4][NT];
__device__ int   g_off[4][NT + 1];
__device__ int   g_bsum[4][NB];
__device__ int   g_boff[4][NB];

// ---------------- device helpers --------------------------------------------
// GEMM tile: H[tile*128 .. +127, 0..63] = X @ W,  8x4 microtile per thread
template <int K>
__device__ __forceinline__ void gemm_tile(const float* __restrict__ X,
                                          const float* __restrict__ W,
                                          float* __restrict__ Hout,
                                          int N, int tile)
{
    __shared__ float Xt[16][132];
    __shared__ float Ws[16][64];
    const int tid = threadIdx.x;
    const int tc = tid & 15;
    const int tr = tid >> 4;
    const int row0 = tile * 128;

    const int f0 = tid * 2;
    const int xrow0 = f0 >> 2, xkq0 = (f0 & 3) * 4;
    const int xrow1 = (f0 + 1) >> 2, xkq1 = ((f0 + 1) & 3) * 4;
    const int wrow = tid >> 4;
    const int wc4 = (tid & 15) * 4;

    const float4 zf4 = make_float4(0.f, 0.f, 0.f, 0.f);
    float4 xg0, xg1, wg;
    {
        int gr0 = row0 + xrow0, gr1 = row0 + xrow1;
        xg0 = (gr0 < N) ? *(const float4*)(X + (size_t)gr0 * K + xkq0) : zf4;
        xg1 = (gr1 < N) ? *(const float4*)(X + (size_t)gr1 * K + xkq1) : zf4;
        wg  = *(const float4*)(W + (size_t)wrow * 64 + wc4);
    }

    float acc[8][4];
    #pragma unroll
    for (int i = 0; i < 8; i++)
        #pragma unroll
        for (int j = 0; j < 4; j++) acc[i][j] = 0.f;

    #pragma unroll 1
    for (int kc = 0; kc < K; kc += 16) {
        Xt[xkq0 + 0][xrow0] = xg0.x; Xt[xkq0 + 1][xrow0] = xg0.y;
        Xt[xkq0 + 2][xrow0] = xg0.z; Xt[xkq0 + 3][xrow0] = xg0.w;
        Xt[xkq1 + 0][xrow1] = xg1.x; Xt[xkq1 + 1][xrow1] = xg1.y;
        Xt[xkq1 + 2][xrow1] = xg1.z; Xt[xkq1 + 3][xrow1] = xg1.w;
        *(float4*)&Ws[wrow][wc4] = wg;
        __syncthreads();
        if (kc + 16 < K) {
            int kn = kc + 16;
            int gr0 = row0 + xrow0, gr1 = row0 + xrow1;
            xg0 = (gr0 < N) ? *(const float4*)(X + (size_t)gr0 * K + kn + xkq0) : zf4;
            xg1 = (gr1 < N) ? *(const float4*)(X + (size_t)gr1 * K + kn + xkq1) : zf4;
            wg  = *(const float4*)(W + (size_t)(kn + wrow) * 64 + wc4);
        }
        #pragma unroll
        for (int k = 0; k < 16; k++) {
            float4 x0 = *(const float4*)&Xt[k][tr * 8];
            float4 x1 = *(const float4*)&Xt[k][tr * 8 + 4];
            float4 wv = *(const float4*)&Ws[k][tc * 4];
            float xs[8] = {x0.x, x0.y, x0.z, x0.w, x1.x, x1.y, x1.z, x1.w};
            float wf[4] = {wv.x, wv.y, wv.z, wv.w};
            #pragma unroll
            for (int i = 0; i < 8; i++)
                #pragma unroll
                for (int j = 0; j < 4; j++)
                    acc[i][j] += xs[i] * wf[j];
        }
        __syncthreads();
    }
    #pragma unroll
    for (int i = 0; i < 8; i++) {
        int gr = row0 + tr * 8 + i;
        if (gr < N)
            *(float4*)(Hout + (size_t)gr * 64 + tc * 4) =
                make_float4(acc[i][0], acc[i][1], acc[i][2], acc[i][3]);
    }
}

// warp computes alpha[ais[j]][node] = X[node,:] . g_v[vis[j]]
__device__ __forceinline__ void alpha_node(const float* __restrict__ X, int node,
                                           int lane, int K,
                                           const int* vis, const int* ais, int nv)
{
    const float* xr = X + (size_t)node * K;
    int nt = K >> 5;
    float xv[4];
    #pragma unroll
    for (int t = 0; t < 4; t++) xv[t] = (t < nt) ? xr[lane + 32 * t] : 0.f;
    #pragma unroll 4
    for (int j = 0; j < nv; j++) {
        const float* v = g_v[vis[j]];
        float p = 0.f;
        #pragma unroll
        for (int t = 0; t < 4; t++) if (t < nt) p += xv[t] * v[lane + 32 * t];
        #pragma unroll
        for (int d = 16; d; d >>= 1) p += __shfl_xor_sync(0xffffffffu, p, d);
        if (lane == 0) g_alpha[ais[j]][node] = p;
    }
}

// warp-per-node softmax aggregation; edge payload already holds w=exp(logit)
__device__ __forceinline__ void gat_node(int rel, int hIdx, int node, int lane,
                                         float& o0, float& o1)
{
    const int2* __restrict__ edges = g_edges[rel];
    const float* __restrict__ H = g_H[hIdx];
    int s = g_off[rel][node], e = g_off[rel][node + 1];
    float a0 = 0.f, a1 = 0.f;
    int i = s;
    for (; i + 2 <= e; i += 2) {
        int2 e0 = edges[i], e1 = edges[i + 1];
        float w0 = __int_as_float(e0.y), w1 = __int_as_float(e1.y);
        const float* h0 = H + (size_t)e0.x * 64;
        const float* h1 = H + (size_t)e1.x * 64;
        a0 += w0 * h0[lane];      a1 += w0 * h0[lane + 32];
        a0 += w1 * h1[lane];      a1 += w1 * h1[lane + 32];
    }
    if (i < e) {
        int2 e0 = edges[i];
        float w0 = __int_as_float(e0.y);
        const float* h0 = H + (size_t)e0.x * 64;
        a0 += w0 * h0[lane];      a1 += w0 * h0[lane + 32];
    }
    float inv = 1.f / (g_den[rel][node] + 1e-16f);
    o0 = a0 * inv;
    o1 = a1 * inv;
}

// ---------------- K1: zero scratch + v = W @ a -------------------------------
__global__ __launch_bounds__(256) void init_kernel(
    const float* W_tt, const float* W_dts, const float* W_dtd,
    const float* W_dd, const float* W_tds, const float* W_tdd,
    const float* a_tts, const float* a_ttd, const float* a_dts, const float* a_dtd,
    const float* a_dds, const float* a_ddd, const float* a_tds, const float* a_tdd)
{
    int b = blockIdx.x;
    if (b < NB) {
        int i = b * 256 + threadIdx.x;           // int4 index, 50000 per array
        if (i < 50000) {
            ((int4*)g_cnt)[i] = make_int4(0, 0, 0, 0);
            ((int4*)g_cur)[i] = make_int4(0, 0, 0, 0);
            ((float4*)g_den)[i] = make_float4(0.f, 0.f, 0.f, 0.f);
        }
        return;
    }
    int j = b - NB;
    const float* W = nullptr; const float* a = nullptr; int K = 128;
    switch (j) {
        case 0: W = W_tt;  a = a_tts; break;
        case 1: W = W_tt;  a = a_ttd; break;
        case 2: W = W_dts; a = a_dts; break;
        case 3: W = W_dtd; a = a_dtd; break;
        case 4: W = W_dd;  a = a_dds; break;
        case 5: W = W_dd;  a = a_ddd; break;
        case 6: W = W_tds; a = a_tds; K = 64; break;
        case 7: W = W_tdd; a = a_tdd; break;
    }
    int k = threadIdx.x;
    if (k < K) {
        float s = 0.f;
        #pragma unroll
        for (int c = 0; c < 64; c++) s += W[k * 64 + c] * a[c];
        g_v[j][k] = s;
    }
}

// ---------------- K2: fused GEMMx3 + hist x4 + alpha x2 ----------------------
__global__ __launch_bounds__(256) void phase1_kernel(
    const float* __restrict__ xt, const float* __restrict__ xd,
    const float* __restrict__ W_tt, const float* __restrict__ W_dts,
    const float* __restrict__ W_dd,
    const int* __restrict__ tt_d, const int* __restrict__ dt_d,
    const int* __restrict__ dd_d, const int* __restrict__ td_d)
{
    int b = blockIdx.x;
    if (b < 3 * GBK) {
        int which = b / GBK, tile = b % GBK;
        const float* X = (which == 0) ? xt : xd;
        const float* W = (which == 0) ? W_tt : (which == 1) ? W_dts : W_dd;
        gemm_tile<128>(X, W, g_H[which], NT, tile);
        return;
    }
    b -= 3 * GBK;
    if (b < 4 * EB) {                          // histograms
        int rel = b / EB;
        int i = (b % EB) * 256 + threadIdx.x;
        const int* d = (rel == 0) ? tt_d : (rel == 1) ? dt_d
                     : (rel == 2) ? dd_d : td_d;
        if (i < NE) atomicAdd(&g_cnt[rel][d[i]], 1);
        return;
    }
    b -= 4 * EB;                               // alphas
    int wid = threadIdx.x >> 5, lane = threadIdx.x & 31;
    if (b < AB) {
        int node = b * 8 + wid;
        if (node >= NT) return;
        const int vis[3] = {0, 1, 3}, ais[3] = {0, 1, 3};
        alpha_node(xt, node, lane, 128, vis, ais, 3);
    } else {
        int node = (b - AB) * 8 + wid;
        if (node >= NT) return;
        const int vis[4] = {2, 4, 5, 7}, ais[4] = {2, 4, 5, 7};
        alpha_node(xd, node, lane, 128, vis, ais, 4);
    }
}

// ---------------- 3-phase scan ------------------------------------------------
__global__ void bsum_kernel() {
    int rel = blockIdx.y;
    int idx = blockIdx.x * 256 + threadIdx.x;
    int v = (idx < NT) ? g_cnt[rel][idx] : 0;
    #pragma unroll
    for (int d = 16; d; d >>= 1) v += __shfl_xor_sync(0xffffffffu, v, d);
    __shared__ int s[8];
    int lane = threadIdx.x & 31, wid = threadIdx.x >> 5;
    if (lane == 0) s[wid] = v;
    __syncthreads();
    if (threadIdx.x == 0) {
        int t = 0;
        #pragma unroll
        for (int i = 0; i < 8; i++) t += s[i];
        g_bsum[rel][blockIdx.x] = t;
    }
}

__global__ void bscan_kernel() {
    __shared__ int wsum[8];
    int tid = threadIdx.x, lane = tid & 31, wid = tid >> 5;
    for (int rel = 0; rel < 4; rel++) {
        int v = (tid < NB) ? g_bsum[rel][tid] : 0;
        int x = v;
        #pragma unroll
        for (int d = 1; d < 32; d <<= 1) {
            int y = __shfl_up_sync(0xffffffffu, x, d);
            if (lane >= d) x += y;
        }
        if (lane == 31) wsum[wid] = x;
        __syncthreads();
        if (wid == 0) {
            int sv = (lane < 8) ? wsum[lane] : 0;
            #pragma unroll
            for (int d = 1; d < 8; d <<= 1) {
                int y = __shfl_up_sync(0xffffffffu, sv, d);
                if (lane >= d) sv += y;
            }
            if (lane < 8) wsum[lane] = sv;
        }
        __syncthreads();
        int incl = x + (wid ? wsum[wid - 1] : 0);
        if (tid < NB) g_boff[rel][tid] = incl - v;
        __syncthreads();
    }
}

__global__ void off_kernel() {
    int rel = blockIdx.y;
    int idx = blockIdx.x * 256 + threadIdx.x;
    int v = (idx < NT) ? g_cnt[rel][idx] : 0;
    __shared__ int wsum[8];
    int lane = threadIdx.x & 31, wid = threadIdx.x >> 5;
    int x = v;
    #pragma unroll
    for (int d = 1; d < 32; d <<= 1) {
        int y = __shfl_up_sync(0xffffffffu, x, d);
        if (lane >= d) x += y;
    }
    if (lane == 31) wsum[wid] = x;
    __syncthreads();
    if (wid == 0) {
        int sv = (lane < 8) ? wsum[lane] : 0;
        #pragma unroll
        for (int d = 1; d < 8; d <<= 1) {
            int y = __shfl_up_sync(0xffffffffu, sv, d);
            if (lane >= d) sv += y;
        }
        if (lane < 8) wsum[lane] = sv;
    }
    __syncthreads();
    int incl = x + (wid ? wsum[wid - 1] : 0) + g_boff[rel][blockIdx.x];
    if (idx < NT) g_off[rel][idx + 1] = incl;
    if (idx == 0) g_off[rel][0] = 0;
}

// ---------------- scatter: bucket edges, payload w=exp(l), accumulate den ----
__device__ __forceinline__ void scatter_edge(const int* __restrict__ sp,
                                             const int* __restrict__ dp,
                                             int rel, int as, int ad, int i)
{
    int s = sp[i], d = dp[i];
    float l = g_alpha[as][s] + g_alpha[ad][d];
    l = (l > 0.f) ? l : NEG_SLOPE * l;
    float w = __expf(l);
    atomicAdd(&g_den[rel][d], w);
    int pos = g_off[rel][d] + atomicAdd(&g_cur[rel][d], 1);
    g_edges[rel][pos] = make_int2(s, __float_as_int(w));
}

__global__ void scatter3_kernel(const int* s0, const int* d0,
                                const int* s1, const int* d1,
                                const int* s2, const int* d2)
{
    int rel = blockIdx.x / EB;
    int i = (blockIdx.x % EB) * 256 + threadIdx.x;
    if (i >= NE) return;
    if (rel == 0)      scatter_edge(s0, d0, 0, 0, 1, i);
    else if (rel == 1) scatter_edge(s1, d1, 1, 2, 3, i);
    else               scatter_edge(s2, d2, 2, 4, 5, i);
}

__global__ void scatter1_kernel(const int* s3, const int* d3)
{
    int i = blockIdx.x * 256 + threadIdx.x;
    if (i >= NE) return;
    scatter_edge(s3, d3, 3, 6, 7, i);
}

// ---------------- aggA: target (tt+dt) final + drug dd partial ---------------
__global__ __launch_bounds__(256) void aggA_kernel(
    const float* __restrict__ b_tt, const float* __restrict__ b_dt,
    const float* __restrict__ b_dd,
    float* __restrict__ out_t, float* __restrict__ out_d)
{
    int b = blockIdx.x;
    int wid = threadIdx.x >> 5, lane = threadIdx.x & 31;
    if (b < AB) {
        int node = b * 8 + wid;
        if (node >= NT) return;
        float a0, a1, c0, c1;
        gat_node(0, 0, node, lane, a0, a1);
        gat_node(1, 1, node, lane, c0, c1);
        float* orow = out_t + (size_t)node * 64;
        orow[lane]      = 0.5f * (a0 + b_tt[lane]      + c0 + b_dt[lane]);
        orow[lane + 32] = 0.5f * (a1 + b_tt[lane + 32] + c1 + b_dt[lane + 32]);
    } else {
        int node = (b - AB) * 8 + wid;
        if (node >= NT) return;
        float a0, a1;
        gat_node(2, 2, node, lane, a0, a1);
        float* orow = out_d + (size_t)node * 64;
        orow[lane]      = a0 + b_dd[lane];          // unscaled partial
        orow[lane + 32] = a1 + b_dd[lane + 32];
    }
}

// ---------------- phase2: gemm_td + alpha_td (both on out_t) -----------------
__global__ __launch_bounds__(256) void phase2_kernel(
    const float* __restrict__ out_t, const float* __restrict__ W_tds)
{
    int b = blockIdx.x;
    if (b < GBK) {
        gemm_tile<64>(out_t, W_tds, g_H[3], NT, b);
        return;
    }
    b -= GBK;
    int wid = threadIdx.x >> 5, lane = threadIdx.x & 31;
    int node = b * 8 + wid;
    if (node >= NT) return;
    const int vis[1] = {6}, ais[1] = {6};
    alpha_node(out_t, node, lane, 64, vis, ais, 1);
}

// ---------------- aggB: drug final = 0.5*(dd_partial + gat_td + b_td) --------
__global__ __launch_bounds__(256) void aggB_kernel(
    const float* __restrict__ b_td, float* __restrict__ out_d)
{
    int wid = threadIdx.x >> 5, lane = threadIdx.x & 31;
    int node = blockIdx.x * 8 + wid;
    if (node >= NT) return;
    float a0, a1;
    gat_node(3, 3, node, lane, a0, a1);
    float* orow = out_d + (size_t)node * 64;
    orow[lane]      = 0.5f * (orow[lane]      + a0 + b_td[lane]);
    orow[lane + 32] = 0.5f * (orow[lane + 32] + a1 + b_td[lane + 32]);
}

// ---------------- launch ------------------------------------------------------
extern "C" void kernel_launch(void* const* d_in, const int* in_sizes, int n_in,
                              void* d_out, int out_size)
{
    const float* x_target   = (const float*)d_in[0];
    const float* x_drug     = (const float*)d_in[1];
    const int*   ei_tt      = (const int*)d_in[2];
    const int*   ei_dt      = (const int*)d_in[3];
    const int*   ei_dd      = (const int*)d_in[4];
    const int*   ei_td      = (const int*)d_in[5];
    const float* W_tt       = (const float*)d_in[6];
    const float* att_tt_src = (const float*)d_in[7];
    const float* att_tt_dst = (const float*)d_in[8];
    const float* b_tt       = (const float*)d_in[9];
    const float* W_dt_src   = (const float*)d_in[10];
    const float* W_dt_dst   = (const float*)d_in[11];
    const float* att_dt_src = (const float*)d_in[12];
    const float* att_dt_dst = (const float*)d_in[13];
    const float* b_dt       = (const float*)d_in[14];
    const float* W_dd       = (const float*)d_in[15];
    const float* att_dd_src = (const float*)d_in[16];
    const float* att_dd_dst = (const float*)d_in[17];
    const float* b_dd       = (const float*)d_in[18];
    const float* W_td_src   = (const float*)d_in[19];
    const float* W_td_dst   = (const float*)d_in[20];
    const float* att_td_src = (const float*)d_in[21];
    const float* att_td_dst = (const float*)d_in[22];
    const float* b_td       = (const float*)d_in[23];

    float* out_t = (float*)d_out;
    float* out_d = out_t + (size_t)NT * 64;

    init_kernel<<<NB + 8, 256>>>(W_tt, W_dt_src, W_dt_dst, W_dd, W_td_src, W_td_dst,
                                 att_tt_src, att_tt_dst, att_dt_src, att_dt_dst,
                                 att_dd_src, att_dd_dst, att_td_src, att_td_dst);

    phase1_kernel<<<3 * GBK + 4 * EB + 2 * AB, 256>>>(
        x_target, x_drug, W_tt, W_dt_src, W_dd,
        ei_tt + NE, ei_dt + NE, ei_dd + NE, ei_td + NE);

    bsum_kernel<<<dim3(NB, 4), 256>>>();
    bscan_kernel<<<1, 256>>>();
    off_kernel<<<dim3(NB, 4), 256>>>();

    scatter3_kernel<<<3 * EB, 256>>>(ei_tt, ei_tt + NE,
                                     ei_dt, ei_dt + NE,
                                     ei_dd, ei_dd + NE);

    aggA_kernel<<<2 * AB, 256>>>(b_tt, b_dt, b_dd, out_t, out_d);

    phase2_kernel<<<GBK + AB, 256>>>(out_t, W_td_src);

    scatter1_kernel<<<EB, 256>>>(ei_td, ei_td + NE);

    aggB_kernel<<<AB, 256>>>(b_td, out_d);
}

// round 4
// speedup vs baseline: 1.1475x; 1.1475x over previous
#include <cuda_runtime.h>
#include <cuda_fp16.h>

#define NT  50000
#define NE  800000
#define NEG_SLOPE 0.2f
#define NB  196        // ceil(50000/256)
#define GBK 391        // ceil(50000/128) gemm row tiles
#define AB  6250       // warp-per-node blocks (8 nodes/block)
#define EB  3125       // ceil(800000/256) edge blocks

// ---------------- scratch (static device globals) ---------------------------
__device__ __half g_H[4][(size_t)NT * 64];  // 0=tt_src,1=dt_src,2=dd_src,3=td_src
__device__ float  g_alpha[8][NT];
__device__ float  g_v[8][128];
__device__ int2   g_edges[4][NE];           // {src, exp(logit) bits}
__device__ int    g_cnt[4][NT];
__device__ int    g_cur[4][NT];
__device__ int    g_off[4][NT + 1];
__device__ int    g_bsum[4][NB];
__device__ int    g_boff[4][NB];

// ---------------- K1: zero scratch + v = W @ a -------------------------------
__global__ __launch_bounds__(256) void init_kernel(
    const float* W_tt, const float* W_dts, const float* W_dtd,
    const float* W_dd, const float* W_tds, const float* W_tdd,
    const float* a_tts, const float* a_ttd, const float* a_dts, const float* a_dtd,
    const float* a_dds, const float* a_ddd, const float* a_tds, const float* a_tdd)
{
    int b = blockIdx.x;
    if (b < NB) {
        int i = b * 256 + threadIdx.x;          // int4 index, covers 4*50000 ints
        if (i < 50000) {
            ((int4*)g_cnt)[i] = make_int4(0, 0, 0, 0);
            ((int4*)g_cur)[i] = make_int4(0, 0, 0, 0);
        }
        return;
    }
    int j = b - NB;
    const float* W = nullptr; const float* a = nullptr; int K = 128;
    switch (j) {
        case 0: W = W_tt;  a = a_tts; break;
        case 1: W = W_tt;  a = a_ttd; break;
        case 2: W = W_dts; a = a_dts; break;
        case 3: W = W_dtd; a = a_dtd; break;
        case 4: W = W_dd;  a = a_dds; break;
        case 5: W = W_dd;  a = a_ddd; break;
        case 6: W = W_tds; a = a_tds; K = 64; break;
        case 7: W = W_tdd; a = a_tdd; break;
    }
    int k = threadIdx.x;
    if (k < K) {
        float s = 0.f;
        #pragma unroll
        for (int c = 0; c < 64; c++) s += W[k * 64 + c] * a[c];
        g_v[j][k] = s;
    }
}

// ---------------- histogram (4 relations) ------------------------------------
__global__ void hist4_kernel(const int* __restrict__ d0, const int* __restrict__ d1,
                             const int* __restrict__ d2, const int* __restrict__ d3) {
    int i = blockIdx.x * blockDim.x + threadIdx.x;
    int rel = blockIdx.y;
    const int* d = (rel == 0) ? d0 : (rel == 1) ? d1 : (rel == 2) ? d2 : d3;
    if (i < NE) atomicAdd(&g_cnt[rel][d[i]], 1);
}

// ---------------- 3-phase scan ------------------------------------------------
__global__ void bsum_kernel() {
    int rel = blockIdx.y;
    int idx = blockIdx.x * 256 + threadIdx.x;
    int v = (idx < NT) ? g_cnt[rel][idx] : 0;
    #pragma unroll
    for (int d = 16; d; d >>= 1) v += __shfl_xor_sync(0xffffffffu, v, d);
    __shared__ int s[8];
    int lane = threadIdx.x & 31, wid = threadIdx.x >> 5;
    if (lane == 0) s[wid] = v;
    __syncthreads();
    if (threadIdx.x == 0) {
        int t = 0;
        #pragma unroll
        for (int i = 0; i < 8; i++) t += s[i];
        g_bsum[rel][blockIdx.x] = t;
    }
}

__global__ void bscan_kernel() {
    __shared__ int wsum[8];
    int tid = threadIdx.x, lane = tid & 31, wid = tid >> 5;
    for (int rel = 0; rel < 4; rel++) {
        int v = (tid < NB) ? g_bsum[rel][tid] : 0;
        int x = v;
        #pragma unroll
        for (int d = 1; d < 32; d <<= 1) {
            int y = __shfl_up_sync(0xffffffffu, x, d);
            if (lane >= d) x += y;
        }
        if (lane == 31) wsum[wid] = x;
        __syncthreads();
        if (wid == 0) {
            int sv = (lane < 8) ? wsum[lane] : 0;
            #pragma unroll
            for (int d = 1; d < 8; d <<= 1) {
                int y = __shfl_up_sync(0xffffffffu, sv, d);
                if (lane >= d) sv += y;
            }
            if (lane < 8) wsum[lane] = sv;
        }
        __syncthreads();
        int incl = x + (wid ? wsum[wid - 1] : 0);
        if (tid < NB) g_boff[rel][tid] = incl - v;
        __syncthreads();
    }
}

__global__ void off_kernel() {
    int rel = blockIdx.y;
    int idx = blockIdx.x * 256 + threadIdx.x;
    int v = (idx < NT) ? g_cnt[rel][idx] : 0;
    __shared__ int wsum[8];
    int lane = threadIdx.x & 31, wid = threadIdx.x >> 5;
    int x = v;
    #pragma unroll
    for (int d = 1; d < 32; d <<= 1) {
        int y = __shfl_up_sync(0xffffffffu, x, d);
        if (lane >= d) x += y;
    }
    if (lane == 31) wsum[wid] = x;
    __syncthreads();
    if (wid == 0) {
        int sv = (lane < 8) ? wsum[lane] : 0;
        #pragma unroll
        for (int d = 1; d < 8; d <<= 1) {
            int y = __shfl_up_sync(0xffffffffu, sv, d);
            if (lane >= d) sv += y;
        }
        if (lane < 8) wsum[lane] = sv;
    }
    __syncthreads();
    int incl = x + (wid ? wsum[wid - 1] : 0) + g_boff[rel][blockIdx.x];
    if (idx < NT) g_off[rel][idx + 1] = incl;
    if (idx == 0) g_off[rel][0] = 0;
}

// ---------------- alpha: warp per node, up to 4 vectors -----------------------
__global__ void alpha_kernel(const float* __restrict__ X, int N, int K,
                             int vi0, int vi1, int vi2, int vi3, int nv)
{
    int warp = (blockIdx.x * blockDim.x + threadIdx.x) >> 5;
    int lane = threadIdx.x & 31;
    if (warp >= N) return;
    const float* xr = X + (size_t)warp * K;
    int nt = K >> 5;
    float xv[4];
    #pragma unroll
    for (int t = 0; t < 4; t++) xv[t] = (t < nt) ? xr[lane + 32 * t] : 0.f;
    int vis[4] = {vi0, vi1, vi2, vi3};
    for (int j = 0; j < nv; j++) {
        const float* v = g_v[vis[j]];
        float p = 0.f;
        #pragma unroll
        for (int t = 0; t < 4; t++) if (t < nt) p += xv[t] * v[lane + 32 * t];
        #pragma unroll
        for (int d = 16; d; d >>= 1) p += __shfl_xor_sync(0xffffffffu, p, d);
        if (lane == 0) g_alpha[vis[j]][warp] = p;
    }
}

// ---------------- GEMM: H(half) = X[N,K] @ W[K,64], 128x64 tile ---------------
template <int K>
__global__ __launch_bounds__(256) void gemm_kernel(
    const float* __restrict__ X, const float* __restrict__ W, int outIdx, int N)
{
    __shared__ float Xt[16][132];
    __shared__ float Ws[16][64];
    __half* __restrict__ Hout = g_H[outIdx];
    const int tid = threadIdx.x;
    const int tc = tid & 15;
    const int tr = tid >> 4;
    const int row0 = blockIdx.x * 128;

    const int f0 = tid * 2;
    const int xrow0 = f0 >> 2, xkq0 = (f0 & 3) * 4;
    const int xrow1 = (f0 + 1) >> 2, xkq1 = ((f0 + 1) & 3) * 4;
    const int wrow = tid >> 4;
    const int wc4 = (tid & 15) * 4;

    const float4 zf4 = make_float4(0.f, 0.f, 0.f, 0.f);
    float4 xg0, xg1, wg;
    {
        int gr0 = row0 + xrow0, gr1 = row0 + xrow1;
        xg0 = (gr0 < N) ? *(const float4*)(X + (size_t)gr0 * K + xkq0) : zf4;
        xg1 = (gr1 < N) ? *(const float4*)(X + (size_t)gr1 * K + xkq1) : zf4;
        wg  = *(const float4*)(W + (size_t)wrow * 64 + wc4);
    }

    float acc[8][4];
    #pragma unroll
    for (int i = 0; i < 8; i++)
        #pragma unroll
        for (int j = 0; j < 4; j++) acc[i][j] = 0.f;

    #pragma unroll 1
    for (int kc = 0; kc < K; kc += 16) {
        Xt[xkq0 + 0][xrow0] = xg0.x; Xt[xkq0 + 1][xrow0] = xg0.y;
        Xt[xkq0 + 2][xrow0] = xg0.z; Xt[xkq0 + 3][xrow0] = xg0.w;
        Xt[xkq1 + 0][xrow1] = xg1.x; Xt[xkq1 + 1][xrow1] = xg1.y;
        Xt[xkq1 + 2][xrow1] = xg1.z; Xt[xkq1 + 3][xrow1] = xg1.w;
        *(float4*)&Ws[wrow][wc4] = wg;
        __syncthreads();
        if (kc + 16 < K) {
            int kn = kc + 16;
            int gr0 = row0 + xrow0, gr1 = row0 + xrow1;
            xg0 = (gr0 < N) ? *(const float4*)(X + (size_t)gr0 * K + kn + xkq0) : zf4;
            xg1 = (gr1 < N) ? *(const float4*)(X + (size_t)gr1 * K + kn + xkq1) : zf4;
            wg  = *(const float4*)(W + (size_t)(kn + wrow) * 64 + wc4);
        }
        #pragma unroll
        for (int k = 0; k < 16; k++) {
            float4 x0 = *(const float4*)&Xt[k][tr * 8];
            float4 x1 = *(const float4*)&Xt[k][tr * 8 + 4];
            float4 wv = *(const float4*)&Ws[k][tc * 4];
            float xs[8] = {x0.x, x0.y, x0.z, x0.w, x1.x, x1.y, x1.z, x1.w};
            float wf[4] = {wv.x, wv.y, wv.z, wv.w};
            #pragma unroll
            for (int i = 0; i < 8; i++)
                #pragma unroll
                for (int j = 0; j < 4; j++)
                    acc[i][j] += xs[i] * wf[j];
        }
        __syncthreads();
    }
    #pragma unroll
    for (int i = 0; i < 8; i++) {
        int gr = row0 + tr * 8 + i;
        if (gr < N) {
            __half2 h0 = __floats2half2_rn(acc[i][0], acc[i][1]);
            __half2 h1 = __floats2half2_rn(acc[i][2], acc[i][3]);
            __half2* dst = (__half2*)(Hout + (size_t)gr * 64 + tc * 4);
            dst[0] = h0;
            dst[1] = h1;
        }
    }
}

// ---------------- scatter: bucket edges, payload w=exp(l) --------------------
__device__ __forceinline__ void scatter_edge(const int* __restrict__ sp,
                                             const int* __restrict__ dp,
                                             int rel, int as, int ad, int i)
{
    int s = sp[i], d = dp[i];
    float l = g_alpha[as][s] + g_alpha[ad][d];
    l = (l > 0.f) ? l : NEG_SLOPE * l;
    float w = __expf(l);
    int pos = g_off[rel][d] + atomicAdd(&g_cur[rel][d], 1);
    g_edges[rel][pos] = make_int2(s, __float_as_int(w));
}

__global__ void scatter3_kernel(const int* s0, const int* d0,
                                const int* s1, const int* d1,
                                const int* s2, const int* d2)
{
    int rel = blockIdx.x / EB;
    int i = (blockIdx.x % EB) * 256 + threadIdx.x;
    if (i >= NE) return;
    if (rel == 0)      scatter_edge(s0, d0, 0, 0, 1, i);
    else if (rel == 1) scatter_edge(s1, d1, 1, 2, 3, i);
    else               scatter_edge(s2, d2, 2, 4, 5, i);
}

__global__ void scatter1_kernel(const int* s3, const int* d3)
{
    int i = blockIdx.x * 256 + threadIdx.x;
    if (i >= NE) return;
    scatter_edge(s3, d3, 3, 6, 7, i);
}

// ---------------- per-node GAT aggregation: single pass, half2 H --------------
// thread lane accumulates output cols {2*lane, 2*lane+1}
__device__ __forceinline__ void gat_node(int rel, int node, int lane,
                                         float& o0, float& o1)
{
    const int2* __restrict__ edges = g_edges[rel];
    const __half2* __restrict__ H = (const __half2*)g_H[rel];
    int s = g_off[rel][node], e = g_off[rel][node + 1];
    float den = 0.f, a0 = 0.f, a1 = 0.f;
    int i = s;
    for (; i + 4 <= e; i += 4) {
        int2 e0 = edges[i], e1 = edges[i + 1], e2 = edges[i + 2], e3 = edges[i + 3];
        float w0 = __int_as_float(e0.y), w1 = __int_as_float(e1.y);
        float w2 = __int_as_float(e2.y), w3 = __int_as_float(e3.y);
        float2 f0 = __half22float2(H[(size_t)e0.x * 32 + lane]);
        float2 f1 = __half22float2(H[(size_t)e1.x * 32 + lane]);
        float2 f2 = __half22float2(H[(size_t)e2.x * 32 + lane]);
        float2 f3 = __half22float2(H[(size_t)e3.x * 32 + lane]);
        den += (w0 + w1) + (w2 + w3);
        a0 += w0 * f0.x + w1 * f1.x + w2 * f2.x + w3 * f3.x;
        a1 += w0 * f0.y + w1 * f1.y + w2 * f2.y + w3 * f3.y;
    }
    for (; i < e; i++) {
        int2 e0 = edges[i];
        float w0 = __int_as_float(e0.y);
        float2 f0 = __half22float2(H[(size_t)e0.x * 32 + lane]);
        den += w0;
        a0 += w0 * f0.x;
        a1 += w0 * f0.y;
    }
    float inv = 1.f / (den + 1e-16f);
    o0 = a0 * inv;
    o1 = a1 * inv;
}

// out = 0.5*((gatA + bA) + (gatB + bB)), warp per node
__global__ __launch_bounds__(256) void agg2_kernel(
    int relA, const float* __restrict__ bA,
    int relB, const float* __restrict__ bB,
    float* __restrict__ out, int n)
{
    int warp = (blockIdx.x * blockDim.x + threadIdx.x) >> 5;
    int lane = threadIdx.x & 31;
    if (warp >= n) return;
    float a0, a1, c0, c1;
    gat_node(relA, warp, lane, a0, a1);
    gat_node(relB, warp, lane, c0, c1);
    float2 bA2 = ((const float2*)bA)[lane];
    float2 bB2 = ((const float2*)bB)[lane];
    float2 o;
    o.x = 0.5f * (a0 + bA2.x + c0 + bB2.x);
    o.y = 0.5f * (a1 + bA2.y + c1 + bB2.y);
    ((float2*)(out + (size_t)warp * 64))[lane] = o;
}

// ---------------- launch ------------------------------------------------------
extern "C" void kernel_launch(void* const* d_in, const int* in_sizes, int n_in,
                              void* d_out, int out_size)
{
    const float* x_target   = (const float*)d_in[0];
    const float* x_drug     = (const float*)d_in[1];
    const int*   ei_tt      = (const int*)d_in[2];
    const int*   ei_dt      = (const int*)d_in[3];
    const int*   ei_dd      = (const int*)d_in[4];
    const int*   ei_td      = (const int*)d_in[5];
    const float* W_tt       = (const float*)d_in[6];
    const float* att_tt_src = (const float*)d_in[7];
    const float* att_tt_dst = (const float*)d_in[8];
    const float* b_tt       = (const float*)d_in[9];
    const float* W_dt_src   = (const float*)d_in[10];
    const float* W_dt_dst   = (const float*)d_in[11];
    const float* att_dt_src = (const float*)d_in[12];
    const float* att_dt_dst = (const float*)d_in[13];
    const float* b_dt       = (const float*)d_in[14];
    const float* W_dd       = (const float*)d_in[15];
    const float* att_dd_src = (const float*)d_in[16];
    const float* att_dd_dst = (const float*)d_in[17];
    const float* b_dd       = (const float*)d_in[18];
    const float* W_td_src   = (const float*)d_in[19];
    const float* W_td_dst   = (const float*)d_in[20];
    const float* att_td_src = (const float*)d_in[21];
    const float* att_td_dst = (const float*)d_in[22];
    const float* b_td       = (const float*)d_in[23];

    float* out_t = (float*)d_out;
    float* out_d = out_t + (size_t)NT * 64;

    const int WB = AB;   // 6250 blocks, warp per node

    // zero cursors/counters + v = W@a
    init_kernel<<<NB + 8, 256>>>(W_tt, W_dt_src, W_dt_dst, W_dd, W_td_src, W_td_dst,
                                 att_tt_src, att_tt_dst, att_dt_src, att_dt_dst,
                                 att_dd_src, att_dd_dst, att_td_src, att_td_dst);

    // CSR build
    hist4_kernel<<<dim3(EB, 4), 256>>>(ei_tt + NE, ei_dt + NE, ei_dd + NE, ei_td + NE);
    bsum_kernel<<<dim3(NB, 4), 256>>>();
    bscan_kernel<<<1, 256>>>();
    off_kernel<<<dim3(NB, 4), 256>>>();

    // alphas (v indices double as alpha slots)
    alpha_kernel<<<WB, 256>>>(x_target, NT, 128, 0, 1, 3, 0, 3); // tt_src,tt_dst,dt_dst
    alpha_kernel<<<WB, 256>>>(x_drug,   NT, 128, 2, 4, 5, 7, 4); // dt_src,dd_src,dd_dst,td_dst

    // src-feature GEMMs (fp16 output)
    gemm_kernel<128><<<GBK, 256>>>(x_target, W_tt,     0, NT);
    gemm_kernel<128><<<GBK, 256>>>(x_drug,   W_dt_src, 1, NT);
    gemm_kernel<128><<<GBK, 256>>>(x_drug,   W_dd,     2, NT);

    // bucket edges with w=exp(leakyrelu(logit))
    scatter3_kernel<<<3 * EB, 256>>>(ei_tt, ei_tt + NE,
                                     ei_dt, ei_dt + NE,
                                     ei_dd, ei_dd + NE);

    // x_target_new = 0.5*(gat_tt + gat_dt)
    agg2_kernel<<<WB, 256>>>(0, b_tt, 1, b_dt, out_t, NT);

    // td relation depends on x_target_new
    gemm_kernel<64><<<GBK, 256>>>(out_t, W_td_src, 3, NT);
    alpha_kernel<<<WB, 256>>>(out_t, NT, 64, 6, 0, 0, 0, 1);
    scatter1_kernel<<<EB, 256>>>(ei_td, ei_td + NE);

    // x_drug_new = 0.5*(gat_dd + gat_td)
    agg2_kernel<<<WB, 256>>>(2, b_dd, 3, b_td, out_d, NT);
}

// round 6
// speedup vs baseline: 1.3994x; 1.2195x over previous
#include <cuda_runtime.h>
#include <cuda_fp16.h>
#include <cstdint>

#define NT  50000
#define NE  800000
#define NEG_SLOPE 0.2f
#define NB  196        // ceil(50000/256)
#define GBK 391        // ceil(50000/128) gemm row tiles
#define AB  6250       // warp-per-node blocks (8 nodes/block)
#define EB  3125       // ceil(800000/256) edge blocks

// ---------------- scratch (static device globals) ---------------------------
__device__ __align__(16) __half g_H[4][(size_t)NT * 64]; // relation src features
__device__ __align__(16) __half g_Wh[4][64 * 128];       // W^T as half, [n][k]
__device__ float  g_alpha[8][NT];
__device__ float  g_v[8][128];
__device__ int2   g_edges[4][NE];           // {src, exp(logit) bits}
__device__ int    g_cnt[4][NT];
__device__ int    g_cur[4][NT];
__device__ int    g_off[4][NT + 1];
__device__ int    g_bsum[4][NB];
__device__ int    g_boff[4][NB];

// ---------------- mma helpers -------------------------------------------------
__device__ __forceinline__ uint32_t smem_u32(const void* p) {
    uint32_t a;
    asm("{ .reg .u64 t; cvta.to.shared.u64 t, %1; cvt.u32.u64 %0, t; }"
        : "=r"(a) : "l"(p));
    return a;
}

__device__ __forceinline__ void ldm_x4(uint32_t* r, uint32_t addr) {
    asm volatile("ldmatrix.sync.aligned.m8n8.x4.shared.b16 {%0,%1,%2,%3}, [%4];"
                 : "=r"(r[0]), "=r"(r[1]), "=r"(r[2]), "=r"(r[3]) : "r"(addr));
}
__device__ __forceinline__ void ldm_x2(uint32_t* r, uint32_t addr) {
    asm volatile("ldmatrix.sync.aligned.m8n8.x2.shared.b16 {%0,%1}, [%2];"
                 : "=r"(r[0]), "=r"(r[1]) : "r"(addr));
}
__device__ __forceinline__ void mma16816(float* c, const uint32_t* a, const uint32_t* b) {
    asm volatile(
        "mma.sync.aligned.m16n8k16.row.col.f32.f16.f16.f32 "
        "{%0,%1,%2,%3}, {%4,%5,%6,%7}, {%8,%9}, {%0,%1,%2,%3};"
        : "+f"(c[0]), "+f"(c[1]), "+f"(c[2]), "+f"(c[3])
        : "r"(a[0]), "r"(a[1]), "r"(a[2]), "r"(a[3]), "r"(b[0]), "r"(b[1]));
}

// ---------------- HMMA GEMM: H(half) = X[N,K](f32) @ W[K,64] -----------------
// CTA: 128x64 tile, 8 warps (4 row-blocks x 2 col-blocks), K chunked by 64.
template <int K, int NMAT>
__global__ __launch_bounds__(256) void hmma_gemm(
    const float* __restrict__ Xt, const float* __restrict__ Xd, int w0)
{
    __shared__ __half sA[128][72];   // chunk of A (fp16), +8 pad
    __shared__ __half sB[64][72];    // chunk of B=W^T (fp16), +8 pad

    const int tid = threadIdx.x;
    const int wid = tid >> 5, lane = tid & 31;
    const int which = (NMAT == 1) ? 0 : (int)(blockIdx.x / GBK);
    const int tile  = (NMAT == 1) ? (int)blockIdx.x : (int)(blockIdx.x % GBK);
    const float* __restrict__ X = (NMAT == 1) ? Xt : (which == 0 ? Xt : Xd);
    const __half* __restrict__ Wh = g_Wh[w0 + which];
    __half* __restrict__ Hout = g_H[w0 + which];
    const int row0 = tile * 128;

    const int wr = wid & 3;          // row block (32 rows)
    const int wc = wid >> 2;         // col block (32 cols)

    float acc[2][4][4];
    #pragma unroll
    for (int mi = 0; mi < 2; mi++)
        #pragma unroll
        for (int ni = 0; ni < 4; ni++)
            #pragma unroll
            for (int j = 0; j < 4; j++) acc[mi][ni][j] = 0.f;

    #pragma unroll
    for (int kc = 0; kc < K; kc += 64) {
        // load A chunk: 128 rows x 64 halfs (convert from fp32), 8 iters
        #pragma unroll
        for (int it = 0; it < 8; it++) {
            int idx = tid + it * 256;          // quad index
            int r = idx >> 4, q = (idx & 15) * 4;
            int gr = row0 + r;
            float4 xv = make_float4(0.f, 0.f, 0.f, 0.f);
            if (gr < NT) xv = *(const float4*)(X + (size_t)gr * K + kc + q);
            *(__half2*)&sA[r][q]     = __floats2half2_rn(xv.x, xv.y);
            *(__half2*)&sA[r][q + 2] = __floats2half2_rn(xv.z, xv.w);
        }
        // load B chunk: 64 rows x 64 halfs, 2 iters of uint4 (8 halfs)
        #pragma unroll
        for (int it = 0; it < 2; it++) {
            int idx = tid + it * 256;          // oct index
            int r = idx >> 3, o = (idx & 7) * 8;
            uint4 v = *(const uint4*)(Wh + (size_t)r * K + kc + o);
            *(uint4*)&sB[r][o] = v;
        }
        __syncthreads();

        #pragma unroll
        for (int ks = 0; ks < 4; ks++) {
            int k0 = ks * 16;
            uint32_t af[2][4], bf[4][2];
            #pragma unroll
            for (int mi = 0; mi < 2; mi++) {
                uint32_t addr = smem_u32(&sA[wr * 32 + mi * 16 + (lane & 15)]
                                            [k0 + (lane >> 4) * 8]);
                ldm_x4(af[mi], addr);
            }
            #pragma unroll
            for (int ni = 0; ni < 4; ni++) {
                uint32_t addr = smem_u32(&sB[wc * 32 + ni * 8 + (lane & 7)]
                                            [k0 + ((lane >> 3) & 1) * 8]);
                ldm_x2(bf[ni], addr);
            }
            #pragma unroll
            for (int mi = 0; mi < 2; mi++)
                #pragma unroll
                for (int ni = 0; ni < 4; ni++)
                    mma16816(acc[mi][ni], af[mi], bf[ni]);
        }
        __syncthreads();
    }

    // epilogue: c[0]=D[g][tg*2], c[1]=D[g][tg*2+1], c[2]=D[g+8][..], c[3]
    const int g = lane >> 2, tg = lane & 3;
    #pragma unroll
    for (int mi = 0; mi < 2; mi++) {
        #pragma unroll
        for (int half_ = 0; half_ < 2; half_++) {
            int gr = row0 + wr * 32 + mi * 16 + g + half_ * 8;
            if (gr < NT) {
                __half2* dst = (__half2*)(Hout + (size_t)gr * 64 + wc * 32);
                #pragma unroll
                for (int ni = 0; ni < 4; ni++) {
                    float c0 = acc[mi][ni][half_ * 2];
                    float c1 = acc[mi][ni][half_ * 2 + 1];
                    dst[ni * 4 + tg] = __floats2half2_rn(c0, c1);
                }
            }
        }
    }
}

// ---------------- K1: zero scratch + v = W @ a + W^T half --------------------
__global__ __launch_bounds__(256) void init_kernel(
    const float* W_tt, const float* W_dts, const float* W_dtd,
    const float* W_dd, const float* W_tds, const float* W_tdd,
    const float* a_tts, const float* a_ttd, const float* a_dts, const float* a_dtd,
    const float* a_dds, const float* a_ddd, const float* a_tds, const float* a_tdd)
{
    int b = blockIdx.x;
    if (b < NB) {
        int i = b * 256 + threadIdx.x;          // int4 index, covers 4*50000 ints
        if (i < 50000) {
            ((int4*)g_cnt)[i] = make_int4(0, 0, 0, 0);
            ((int4*)g_cur)[i] = make_int4(0, 0, 0, 0);
        }
        return;
    }
    if (b < NB + 4) {                           // W^T -> half (B layout [n][k])
        int j = b - NB;
        const float* W = (j == 0) ? W_tt : (j == 1) ? W_dts : (j == 2) ? W_dd : W_tds;
        int K = (j == 3) ? 64 : 128;
        for (int i = threadIdx.x; i < 64 * K; i += 256) {
            int n = i / K, k = i % K;
            g_Wh[j][i] = __float2half(W[k * 64 + n]);
        }
        return;
    }
    int j = b - NB - 4;
    const float* W = nullptr; const float* a = nullptr; int K = 128;
    switch (j) {
        case 0: W = W_tt;  a = a_tts; break;
        case 1: W = W_tt;  a = a_ttd; break;
        case 2: W = W_dts; a = a_dts; break;
        case 3: W = W_dtd; a = a_dtd; break;
        case 4: W = W_dd;  a = a_dds; break;
        case 5: W = W_dd;  a = a_ddd; break;
        case 6: W = W_tds; a = a_tds; K = 64; break;
        case 7: W = W_tdd; a = a_tdd; break;
    }
    int k = threadIdx.x;
    if (k < K) {
        float s = 0.f;
        #pragma unroll
        for (int c = 0; c < 64; c++) s += W[k * 64 + c] * a[c];
        g_v[j][k] = s;
    }
}

// ---------------- histogram (4 relations) ------------------------------------
__global__ void hist4_kernel(const int* __restrict__ d0, const int* __restrict__ d1,
                             const int* __restrict__ d2, const int* __restrict__ d3) {
    int i = blockIdx.x * blockDim.x + threadIdx.x;
    int rel = blockIdx.y;
    const int* d = (rel == 0) ? d0 : (rel == 1) ? d1 : (rel == 2) ? d2 : d3;
    if (i < NE) atomicAdd(&g_cnt[rel][d[i]], 1);
}

// ---------------- 3-phase scan ------------------------------------------------
__global__ void bsum_kernel() {
    int rel = blockIdx.y;
    int idx = blockIdx.x * 256 + threadIdx.x;
    int v = (idx < NT) ? g_cnt[rel][idx] : 0;
    #pragma unroll
    for (int d = 16; d; d >>= 1) v += __shfl_xor_sync(0xffffffffu, v, d);
    __shared__ int s[8];
    int lane = threadIdx.x & 31, wid = threadIdx.x >> 5;
    if (lane == 0) s[wid] = v;
    __syncthreads();
    if (threadIdx.x == 0) {
        int t = 0;
        #pragma unroll
        for (int i = 0; i < 8; i++) t += s[i];
        g_bsum[rel][blockIdx.x] = t;
    }
}

__global__ void bscan_kernel() {
    __shared__ int wsum[8];
    int tid = threadIdx.x, lane = tid & 31, wid = tid >> 5;
    for (int rel = 0; rel < 4; rel++) {
        int v = (tid < NB) ? g_bsum[rel][tid] : 0;
        int x = v;
        #pragma unroll
        for (int d = 1; d < 32; d <<= 1) {
            int y = __shfl_up_sync(0xffffffffu, x, d);
            if (lane >= d) x += y;
        }
        if (lane == 31) wsum[wid] = x;
        __syncthreads();
        if (wid == 0) {
            int sv = (lane < 8) ? wsum[lane] : 0;
            #pragma unroll
            for (int d = 1; d < 8; d <<= 1) {
                int y = __shfl_up_sync(0xffffffffu, sv, d);
                if (lane >= d) sv += y;
            }
            if (lane < 8) wsum[lane] = sv;
        }
        __syncthreads();
        int incl = x + (wid ? wsum[wid - 1] : 0);
        if (tid < NB) g_boff[rel][tid] = incl - v;
        __syncthreads();
    }
}

__global__ void off_kernel() {
    int rel = blockIdx.y;
    int idx = blockIdx.x * 256 + threadIdx.x;
    int v = (idx < NT) ? g_cnt[rel][idx] : 0;
    __shared__ int wsum[8];
    int lane = threadIdx.x & 31, wid = threadIdx.x >> 5;
    int x = v;
    #pragma unroll
    for (int d = 1; d < 32; d <<= 1) {
        int y = __shfl_up_sync(0xffffffffu, x, d);
        if (lane >= d) x += y;
    }
    if (lane == 31) wsum[wid] = x;
    __syncthreads();
    if (wid == 0) {
        int sv = (lane < 8) ? wsum[lane] : 0;
        #pragma unroll
        for (int d = 1; d < 8; d <<= 1) {
            int y = __shfl_up_sync(0xffffffffu, sv, d);
            if (lane >= d) sv += y;
        }
        if (lane < 8) wsum[lane] = sv;
    }
    __syncthreads();
    int incl = x + (wid ? wsum[wid - 1] : 0) + g_boff[rel][blockIdx.x];
    if (idx < NT) g_off[rel][idx + 1] = incl;
    if (idx == 0) g_off[rel][0] = 0;
}

// ---------------- alpha: warp per node, up to 4 vectors -----------------------
__global__ void alpha_kernel(const float* __restrict__ X, int N, int K,
                             int vi0, int vi1, int vi2, int vi3, int nv)
{
    int warp = (blockIdx.x * blockDim.x + threadIdx.x) >> 5;
    int lane = threadIdx.x & 31;
    if (warp >= N) return;
    const float* xr = X + (size_t)warp * K;
    int nt = K >> 5;
    float xv[4];
    #pragma unroll
    for (int t = 0; t < 4; t++) xv[t] = (t < nt) ? xr[lane + 32 * t] : 0.f;
    int vis[4] = {vi0, vi1, vi2, vi3};
    for (int j = 0; j < nv; j++) {
        const float* v = g_v[vis[j]];
        float p = 0.f;
        #pragma unroll
        for (int t = 0; t < 4; t++) if (t < nt) p += xv[t] * v[lane + 32 * t];
        #pragma unroll
        for (int d = 16; d; d >>= 1) p += __shfl_xor_sync(0xffffffffu, p, d);
        if (lane == 0) g_alpha[vis[j]][warp] = p;
    }
}

// ---------------- scatter: bucket edges, payload w=exp(l) --------------------
__device__ __forceinline__ void scatter_edge(const int* __restrict__ sp,
                                             const int* __restrict__ dp,
                                             int rel, int as, int ad, int i)
{
    int s = sp[i], d = dp[i];
    float l = g_alpha[as][s] + g_alpha[ad][d];
    l = (l > 0.f) ? l : NEG_SLOPE * l;
    float w = __expf(l);
    int pos = g_off[rel][d] + atomicAdd(&g_cur[rel][d], 1);
    g_edges[rel][pos] = make_int2(s, __float_as_int(w));
}

__global__ void scatter3_kernel(const int* s0, const int* d0,
                                const int* s1, const int* d1,
                                const int* s2, const int* d2)
{
    int rel = blockIdx.x / EB;
    int i = (blockIdx.x % EB) * 256 + threadIdx.x;
    if (i >= NE) return;
    if (rel == 0)      scatter_edge(s0, d0, 0, 0, 1, i);
    else if (rel == 1) scatter_edge(s1, d1, 1, 2, 3, i);
    else               scatter_edge(s2, d2, 2, 4, 5, i);
}

__global__ void scatter1_kernel(const int* s3, const int* d3)
{
    int i = blockIdx.x * 256 + threadIdx.x;
    if (i >= NE) return;
    scatter_edge(s3, d3, 3, 6, 7, i);
}

// ---------------- per-node GAT aggregation: single pass, half2 H --------------
__device__ __forceinline__ void gat_node(int rel, int node, int lane,
                                         float& o0, float& o1)
{
    const int2* __restrict__ edges = g_edges[rel];
    const __half2* __restrict__ H = (const __half2*)g_H[rel];
    int s = g_off[rel][node], e = g_off[rel][node + 1];
    float den = 0.f, a0 = 0.f, a1 = 0.f;
    int i = s;
    for (; i + 4 <= e; i += 4) {
        int2 e0 = edges[i], e1 = edges[i + 1], e2 = edges[i + 2], e3 = edges[i + 3];
        float w0 = __int_as_float(e0.y), w1 = __int_as_float(e1.y);
        float w2 = __int_as_float(e2.y), w3 = __int_as_float(e3.y);
        float2 f0 = __half22float2(H[(size_t)e0.x * 32 + lane]);
        float2 f1 = __half22float2(H[(size_t)e1.x * 32 + lane]);
        float2 f2 = __half22float2(H[(size_t)e2.x * 32 + lane]);
        float2 f3 = __half22float2(H[(size_t)e3.x * 32 + lane]);
        den += (w0 + w1) + (w2 + w3);
        a0 += w0 * f0.x + w1 * f1.x + w2 * f2.x + w3 * f3.x;
        a1 += w0 * f0.y + w1 * f1.y + w2 * f2.y + w3 * f3.y;
    }
    for (; i < e; i++) {
        int2 e0 = edges[i];
        float w0 = __int_as_float(e0.y);
        float2 f0 = __half22float2(H[(size_t)e0.x * 32 + lane]);
        den += w0;
        a0 += w0 * f0.x;
        a1 += w0 * f0.y;
    }
    float inv = 1.f / (den + 1e-16f);
    o0 = a0 * inv;
    o1 = a1 * inv;
}

// out = 0.5*((gatA + bA) + (gatB + bB)); optionally also alpha6 = out . v6
__global__ __launch_bounds__(256) void agg2_kernel(
    int relA, const float* __restrict__ bA,
    int relB, const float* __restrict__ bB,
    float* __restrict__ out, int n, int compute_alpha)
{
    int warp = (blockIdx.x * blockDim.x + threadIdx.x) >> 5;
    int lane = threadIdx.x & 31;
    if (warp >= n) return;
    float a0, a1, c0, c1;
    gat_node(relA, warp, lane, a0, a1);
    gat_node(relB, warp, lane, c0, c1);
    float2 bA2 = ((const float2*)bA)[lane];
    float2 bB2 = ((const float2*)bB)[lane];
    float2 o;
    o.x = 0.5f * (a0 + bA2.x + c0 + bB2.x);
    o.y = 0.5f * (a1 + bA2.y + c1 + bB2.y);
    ((float2*)(out + (size_t)warp * 64))[lane] = o;
    if (compute_alpha) {
        float2 v6 = ((const float2*)g_v[6])[lane];
        float p = o.x * v6.x + o.y * v6.y;
        #pragma unroll
        for (int d = 16; d; d >>= 1) p += __shfl_xor_sync(0xffffffffu, p, d);
        if (lane == 0) g_alpha[6][warp] = p;
    }
}

// ---------------- launch ------------------------------------------------------
extern "C" void kernel_launch(void* const* d_in, const int* in_sizes, int n_in,
                              void* d_out, int out_size)
{
    const float* x_target   = (const float*)d_in[0];
    const float* x_drug     = (const float*)d_in[1];
    const int*   ei_tt      = (const int*)d_in[2];
    const int*   ei_dt      = (const int*)d_in[3];
    const int*   ei_dd      = (const int*)d_in[4];
    const int*   ei_td      = (const int*)d_in[5];
    const float* W_tt       = (const float*)d_in[6];
    const float* att_tt_src = (const float*)d_in[7];
    const float* att_tt_dst = (const float*)d_in[8];
    const float* b_tt       = (const float*)d_in[9];
    const float* W_dt_src   = (const float*)d_in[10];
    const float* W_dt_dst   = (const float*)d_in[11];
    const float* att_dt_src = (const float*)d_in[12];
    const float* att_dt_dst = (const float*)d_in[13];
    const float* b_dt       = (const float*)d_in[14];
    const float* W_dd       = (const float*)d_in[15];
    const float* att_dd_src = (const float*)d_in[16];
    const float* att_dd_dst = (const float*)d_in[17];
    const float* b_dd       = (const float*)d_in[18];
    const float* W_td_src   = (const float*)d_in[19];
    const float* W_td_dst   = (const float*)d_in[20];
    const float* att_td_src = (const float*)d_in[21];
    const float* att_td_dst = (const float*)d_in[22];
    const float* b_td       = (const float*)d_in[23];

    float* out_t = (float*)d_out;
    float* out_d = out_t + (size_t)NT * 64;

    // zero cursors/counters + v = W@a + W^T halves
    init_kernel<<<NB + 12, 256>>>(W_tt, W_dt_src, W_dt_dst, W_dd, W_td_src, W_td_dst,
                                  att_tt_src, att_tt_dst, att_dt_src, att_dt_dst,
                                  att_dd_src, att_dd_dst, att_td_src, att_td_dst);

    // CSR build
    hist4_kernel<<<dim3(EB, 4), 256>>>(ei_tt + NE, ei_dt + NE, ei_dd + NE, ei_td + NE);
    bsum_kernel<<<dim3(NB, 4), 256>>>();
    bscan_kernel<<<1, 256>>>();
    off_kernel<<<dim3(NB, 4), 256>>>();

    // alphas (v indices double as alpha slots)
    alpha_kernel<<<AB, 256>>>(x_target, NT, 128, 0, 1, 3, 0, 3); // tt_src,tt_dst,dt_dst
    alpha_kernel<<<AB, 256>>>(x_drug,   NT, 128, 2, 4, 5, 7, 4); // dt_src,dd_src,dd_dst,td_dst

    // src-feature GEMMs on tensor cores (mma.sync fp16, fp32 accum)
    hmma_gemm<128, 3><<<3 * GBK, 256>>>(x_target, x_drug, 0);

    // bucket edges with w=exp(leakyrelu(logit))
    scatter3_kernel<<<3 * EB, 256>>>(ei_tt, ei_tt + NE,
                                     ei_dt, ei_dt + NE,
                                     ei_dd, ei_dd + NE);

    // x_target_new = 0.5*(gat_tt + gat_dt), fused alpha6 = out . v6
    agg2_kernel<<<AB, 256>>>(0, b_tt, 1, b_dt, out_t, NT, 1);

    // td relation depends on x_target_new
    hmma_gemm<64, 1><<<GBK, 256>>>(out_t, out_t, 3);
    scatter1_kernel<<<EB, 256>>>(ei_td, ei_td + NE);

    // x_drug_new = 0.5*(gat_dd + gat_td)
    agg2_kernel<<<AB, 256>>>(2, b_dd, 3, b_td, out_d, NT, 0);
}

// round 7
// speedup vs baseline: 1.4478x; 1.0346x over previous
#include <cuda_runtime.h>
#include <cuda_fp16.h>
#include <cstdint>

#define NT  50000
#define NE  800000
#define NEG_SLOPE 0.2f
#define NB  196        // ceil(50000/256)
#define GBK 391        // ceil(50000/128) gemm row tiles
#define AB  6250       // warp-per-node blocks (8 nodes/block)
#define EB  3125       // ceil(800000/256) edge blocks

// ---------------- scratch (static device globals) ---------------------------
__device__ __align__(16) __half g_H[4][(size_t)NT * 64]; // relation src features
__device__ __align__(16) __half g_Wh[4][64 * 128];       // W^T as half, [n][k]
__device__ float  g_alpha[8][NT];
__device__ float  g_v[8][128];
__device__ int    g_edges[4][NE];           // src index per bucketed edge
__device__ int    g_cnt[4][NT];             // counts, then reused as cursors
__device__ int    g_off[4][NT + 1];
__device__ int    g_bsum[4][NB];
__device__ int    g_boff[4][NB];

// ---------------- mma helpers -------------------------------------------------
__device__ __forceinline__ uint32_t smem_u32(const void* p) {
    uint32_t a;
    asm("{ .reg .u64 t; cvta.to.shared.u64 t, %1; cvt.u32.u64 %0, t; }"
        : "=r"(a) : "l"(p));
    return a;
}
__device__ __forceinline__ void ldm_x4(uint32_t* r, uint32_t addr) {
    asm volatile("ldmatrix.sync.aligned.m8n8.x4.shared.b16 {%0,%1,%2,%3}, [%4];"
                 : "=r"(r[0]), "=r"(r[1]), "=r"(r[2]), "=r"(r[3]) : "r"(addr));
}
__device__ __forceinline__ void ldm_x2(uint32_t* r, uint32_t addr) {
    asm volatile("ldmatrix.sync.aligned.m8n8.x2.shared.b16 {%0,%1}, [%2];"
                 : "=r"(r[0]), "=r"(r[1]) : "r"(addr));
}
__device__ __forceinline__ void mma16816(float* c, const uint32_t* a, const uint32_t* b) {
    asm volatile(
        "mma.sync.aligned.m16n8k16.row.col.f32.f16.f16.f32 "
        "{%0,%1,%2,%3}, {%4,%5,%6,%7}, {%8,%9}, {%0,%1,%2,%3};"
        : "+f"(c[0]), "+f"(c[1]), "+f"(c[2]), "+f"(c[3])
        : "r"(a[0]), "r"(a[1]), "r"(a[2]), "r"(a[3]), "r"(b[0]), "r"(b[1]));
}

// ---------------- HMMA GEMM: H(half) = X[N,K](f32) @ W[K,64] -----------------
template <int K, int NMAT>
__global__ __launch_bounds__(256) void hmma_gemm(
    const float* __restrict__ Xt, const float* __restrict__ Xd, int w0)
{
    __shared__ __half sA[128][72];
    __shared__ __half sB[64][72];

    const int tid = threadIdx.x;
    const int wid = tid >> 5, lane = tid & 31;
    const int which = (NMAT == 1) ? 0 : (int)(blockIdx.x / GBK);
    const int tile  = (NMAT == 1) ? (int)blockIdx.x : (int)(blockIdx.x % GBK);
    const float* __restrict__ X = (NMAT == 1) ? Xt : (which == 0 ? Xt : Xd);
    const __half* __restrict__ Wh = g_Wh[w0 + which];
    __half* __restrict__ Hout = g_H[w0 + which];
    const int row0 = tile * 128;

    const int wr = wid & 3;
    const int wc = wid >> 2;

    float acc[2][4][4];
    #pragma unroll
    for (int mi = 0; mi < 2; mi++)
        #pragma unroll
        for (int ni = 0; ni < 4; ni++)
            #pragma unroll
            for (int j = 0; j < 4; j++) acc[mi][ni][j] = 0.f;

    #pragma unroll
    for (int kc = 0; kc < K; kc += 64) {
        #pragma unroll
        for (int it = 0; it < 8; it++) {
            int idx = tid + it * 256;
            int r = idx >> 4, q = (idx & 15) * 4;
            int gr = row0 + r;
            float4 xv = make_float4(0.f, 0.f, 0.f, 0.f);
            if (gr < NT) xv = *(const float4*)(X + (size_t)gr * K + kc + q);
            *(__half2*)&sA[r][q]     = __floats2half2_rn(xv.x, xv.y);
            *(__half2*)&sA[r][q + 2] = __floats2half2_rn(xv.z, xv.w);
        }
        #pragma unroll
        for (int it = 0; it < 2; it++) {
            int idx = tid + it * 256;
            int r = idx >> 3, o = (idx & 7) * 8;
            uint4 v = *(const uint4*)(Wh + (size_t)r * K + kc + o);
            *(uint4*)&sB[r][o] = v;
        }
        __syncthreads();

        #pragma unroll
        for (int ks = 0; ks < 4; ks++) {
            int k0 = ks * 16;
            uint32_t af[2][4], bf[4][2];
            #pragma unroll
            for (int mi = 0; mi < 2; mi++) {
                uint32_t addr = smem_u32(&sA[wr * 32 + mi * 16 + (lane & 15)]
                                            [k0 + (lane >> 4) * 8]);
                ldm_x4(af[mi], addr);
            }
            #pragma unroll
            for (int ni = 0; ni < 4; ni++) {
                uint32_t addr = smem_u32(&sB[wc * 32 + ni * 8 + (lane & 7)]
                                            [k0 + ((lane >> 3) & 1) * 8]);
                ldm_x2(bf[ni], addr);
            }
            #pragma unroll
            for (int mi = 0; mi < 2; mi++)
                #pragma unroll
                for (int ni = 0; ni < 4; ni++)
                    mma16816(acc[mi][ni], af[mi], bf[ni]);
        }
        __syncthreads();
    }

    const int g = lane >> 2, tg = lane & 3;
    #pragma unroll
    for (int mi = 0; mi < 2; mi++) {
        #pragma unroll
        for (int half_ = 0; half_ < 2; half_++) {
            int gr = row0 + wr * 32 + mi * 16 + g + half_ * 8;
            if (gr < NT) {
                __half2* dst = (__half2*)(Hout + (size_t)gr * 64 + wc * 32);
                #pragma unroll
                for (int ni = 0; ni < 4; ni++) {
                    float c0 = acc[mi][ni][half_ * 2];
                    float c1 = acc[mi][ni][half_ * 2 + 1];
                    dst[ni * 4 + tg] = __floats2half2_rn(c0, c1);
                }
            }
        }
    }
}

// ---------------- K1: zero counts + v = W @ a + W^T half ---------------------
__global__ __launch_bounds__(256) void init_kernel(
    const float* W_tt, const float* W_dts, const float* W_dtd,
    const float* W_dd, const float* W_tds, const float* W_tdd,
    const float* a_tts, const float* a_ttd, const float* a_dts, const float* a_dtd,
    const float* a_dds, const float* a_ddd, const float* a_tds, const float* a_tdd)
{
    int b = blockIdx.x;
    if (b < NB) {
        int i = b * 256 + threadIdx.x;          // int4 index, covers 4*50000 ints
        if (i < 50000) ((int4*)g_cnt)[i] = make_int4(0, 0, 0, 0);
        return;
    }
    if (b < NB + 4) {                           // W^T -> half (B layout [n][k])
        int j = b - NB;
        const float* W = (j == 0) ? W_tt : (j == 1) ? W_dts : (j == 2) ? W_dd : W_tds;
        int K = (j == 3) ? 64 : 128;
        for (int i = threadIdx.x; i < 64 * K; i += 256) {
            int n = i / K, k = i % K;
            g_Wh[j][i] = __float2half(W[k * 64 + n]);
        }
        return;
    }
    int j = b - NB - 4;
    const float* W = nullptr; const float* a = nullptr; int K = 128;
    switch (j) {
        case 0: W = W_tt;  a = a_tts; break;
        case 1: W = W_tt;  a = a_ttd; break;
        case 2: W = W_dts; a = a_dts; break;
        case 3: W = W_dtd; a = a_dtd; break;
        case 4: W = W_dd;  a = a_dds; break;
        case 5: W = W_dd;  a = a_ddd; break;
        case 6: W = W_tds; a = a_tds; K = 64; break;
        case 7: W = W_tdd; a = a_tdd; break;
    }
    int k = threadIdx.x;
    if (k < K) {
        float s = 0.f;
        #pragma unroll
        for (int c = 0; c < 64; c++) s += W[k * 64 + c] * a[c];
        g_v[j][k] = s;
    }
}

// ---------------- fused hist(4 rel) + alpha(target, drug) --------------------
__device__ __forceinline__ void alpha_node(const float* __restrict__ X, int node,
                                           int lane, const int* vis, int nv)
{
    const float* xr = X + (size_t)node * 128;
    float xv[4];
    #pragma unroll
    for (int t = 0; t < 4; t++) xv[t] = xr[lane + 32 * t];
    #pragma unroll 4
    for (int j = 0; j < nv; j++) {
        const float* v = g_v[vis[j]];
        float p = 0.f;
        #pragma unroll
        for (int t = 0; t < 4; t++) p += xv[t] * v[lane + 32 * t];
        #pragma unroll
        for (int d = 16; d; d >>= 1) p += __shfl_xor_sync(0xffffffffu, p, d);
        if (lane == 0) g_alpha[vis[j]][node] = p;
    }
}

__global__ __launch_bounds__(256) void prep_kernel(
    const float* __restrict__ xt, const float* __restrict__ xd,
    const int* __restrict__ d0, const int* __restrict__ d1,
    const int* __restrict__ d2, const int* __restrict__ d3)
{
    int b = blockIdx.x;
    if (b < 4 * EB) {                          // histograms
        int rel = b / EB;
        int i = (b % EB) * 256 + threadIdx.x;
        const int* d = (rel == 0) ? d0 : (rel == 1) ? d1 : (rel == 2) ? d2 : d3;
        if (i < NE) atomicAdd(&g_cnt[rel][d[i]], 1);
        return;
    }
    b -= 4 * EB;
    int wid = threadIdx.x >> 5, lane = threadIdx.x & 31;
    if (b < AB) {
        int node = b * 8 + wid;
        if (node >= NT) return;
        const int vis[3] = {0, 1, 3};          // tt_src, tt_dst, dt_dst
        alpha_node(xt, node, lane, vis, 3);
    } else {
        int node = (b - AB) * 8 + wid;
        if (node >= NT) return;
        const int vis[4] = {2, 4, 5, 7};       // dt_src, dd_src, dd_dst, td_dst
        alpha_node(xd, node, lane, vis, 4);
    }
}

// ---------------- 3-phase scan ------------------------------------------------
__global__ void bsum_kernel() {
    int rel = blockIdx.y;
    int idx = blockIdx.x * 256 + threadIdx.x;
    int v = (idx < NT) ? g_cnt[rel][idx] : 0;
    #pragma unroll
    for (int d = 16; d; d >>= 1) v += __shfl_xor_sync(0xffffffffu, v, d);
    __shared__ int s[8];
    int lane = threadIdx.x & 31, wid = threadIdx.x >> 5;
    if (lane == 0) s[wid] = v;
    __syncthreads();
    if (threadIdx.x == 0) {
        int t = 0;
        #pragma unroll
        for (int i = 0; i < 8; i++) t += s[i];
        g_bsum[rel][blockIdx.x] = t;
    }
}

__global__ void bscan_kernel() {
    __shared__ int wsum[8];
    int tid = threadIdx.x, lane = tid & 31, wid = tid >> 5;
    for (int rel = 0; rel < 4; rel++) {
        int v = (tid < NB) ? g_bsum[rel][tid] : 0;
        int x = v;
        #pragma unroll
        for (int d = 1; d < 32; d <<= 1) {
            int y = __shfl_up_sync(0xffffffffu, x, d);
            if (lane >= d) x += y;
        }
        if (lane == 31) wsum[wid] = x;
        __syncthreads();
        if (wid == 0) {
            int sv = (lane < 8) ? wsum[lane] : 0;
            #pragma unroll
            for (int d = 1; d < 8; d <<= 1) {
                int y = __shfl_up_sync(0xffffffffu, sv, d);
                if (lane >= d) sv += y;
            }
            if (lane < 8) wsum[lane] = sv;
        }
        __syncthreads();
        int incl = x + (wid ? wsum[wid - 1] : 0);
        if (tid < NB) g_boff[rel][tid] = incl - v;
        __syncthreads();
    }
}

// writes offsets; converts g_cnt into ready-to-use cursors (cursor = excl offset)
__global__ void off_kernel() {
    int rel = blockIdx.y;
    int idx = blockIdx.x * 256 + threadIdx.x;
    int v = (idx < NT) ? g_cnt[rel][idx] : 0;
    __shared__ int wsum[8];
    int lane = threadIdx.x & 31, wid = threadIdx.x >> 5;
    int x = v;
    #pragma unroll
    for (int d = 1; d < 32; d <<= 1) {
        int y = __shfl_up_sync(0xffffffffu, x, d);
        if (lane >= d) x += y;
    }
    if (lane == 31) wsum[wid] = x;
    __syncthreads();
    if (wid == 0) {
        int sv = (lane < 8) ? wsum[lane] : 0;
        #pragma unroll
        for (int d = 1; d < 8; d <<= 1) {
            int y = __shfl_up_sync(0xffffffffu, sv, d);
            if (lane >= d) sv += y;
        }
        if (lane < 8) wsum[lane] = sv;
    }
    __syncthreads();
    int incl = x + (wid ? wsum[wid - 1] : 0) + g_boff[rel][blockIdx.x];
    if (idx < NT) {
        g_off[rel][idx + 1] = incl;
        g_cnt[rel][idx] = incl - v;     // exclusive offset = cursor start
    }
    if (idx == 0) g_off[rel][0] = 0;
}

// ---------------- scatter: all 4 relations, src-only payload ------------------
__global__ void scatter4_kernel(const int* __restrict__ e0, const int* __restrict__ e1,
                                const int* __restrict__ e2, const int* __restrict__ e3)
{
    int rel = blockIdx.x / EB;
    int i = (blockIdx.x % EB) * 256 + threadIdx.x;
    if (i >= NE) return;
    const int* e = (rel == 0) ? e0 : (rel == 1) ? e1 : (rel == 2) ? e2 : e3;
    int s = e[i], d = e[i + NE];
    int pos = atomicAdd(&g_cnt[rel][d], 1);   // returns running position
    g_edges[rel][pos] = s;
}

// ---------------- per-node GAT aggregation (logit+softmax in-place) -----------
__device__ __forceinline__ void gat_node(int rel, int asIdx, float ad,
                                         int node, int lane, float& o0, float& o1)
{
    const int* __restrict__ E = g_edges[rel];
    const __half2* __restrict__ H = (const __half2*)g_H[rel];
    const float* __restrict__ As = g_alpha[asIdx];
    int s = g_off[rel][node], e = g_off[rel][node + 1];
    float den = 0.f, a0 = 0.f, a1 = 0.f;
    int i = s;
    for (; i + 4 <= e; i += 4) {
        int s0 = E[i], s1 = E[i + 1], s2 = E[i + 2], s3 = E[i + 3];
        float l0 = As[s0] + ad, l1 = As[s1] + ad;
        float l2 = As[s2] + ad, l3 = As[s3] + ad;
        float2 f0 = __half22float2(H[(size_t)s0 * 32 + lane]);
        float2 f1 = __half22float2(H[(size_t)s1 * 32 + lane]);
        float2 f2 = __half22float2(H[(size_t)s2 * 32 + lane]);
        float2 f3 = __half22float2(H[(size_t)s3 * 32 + lane]);
        l0 = (l0 > 0.f) ? l0 : NEG_SLOPE * l0;
        l1 = (l1 > 0.f) ? l1 : NEG_SLOPE * l1;
        l2 = (l2 > 0.f) ? l2 : NEG_SLOPE * l2;
        l3 = (l3 > 0.f) ? l3 : NEG_SLOPE * l3;
        float w0 = __expf(l0), w1 = __expf(l1), w2 = __expf(l2), w3 = __expf(l3);
        den += (w0 + w1) + (w2 + w3);
        a0 += w0 * f0.x + w1 * f1.x + w2 * f2.x + w3 * f3.x;
        a1 += w0 * f0.y + w1 * f1.y + w2 * f2.y + w3 * f3.y;
    }
    for (; i < e; i++) {
        int s0 = E[i];
        float l0 = As[s0] + ad;
        float2 f0 = __half22float2(H[(size_t)s0 * 32 + lane]);
        l0 = (l0 > 0.f) ? l0 : NEG_SLOPE * l0;
        float w0 = __expf(l0);
        den += w0;
        a0 += w0 * f0.x;
        a1 += w0 * f0.y;
    }
    float inv = 1.f / (den + 1e-16f);
    o0 = a0 * inv;
    o1 = a1 * inv;
}

// out = 0.5*((gatA + bA) + (gatB + bB)); optionally also alpha6 = out . v6
__global__ __launch_bounds__(256) void agg2_kernel(
    int relA, int asA, int adA, const float* __restrict__ bA,
    int relB, int asB, int adB, const float* __restrict__ bB,
    float* __restrict__ out, int n, int compute_alpha)
{
    int warp = (blockIdx.x * blockDim.x + threadIdx.x) >> 5;
    int lane = threadIdx.x & 31;
    if (warp >= n) return;
    float adAv = g_alpha[adA][warp];
    float adBv = g_alpha[adB][warp];
    float a0, a1, c0, c1;
    gat_node(relA, asA, adAv, warp, lane, a0, a1);
    gat_node(relB, asB, adBv, warp, lane, c0, c1);
    float2 bA2 = ((const float2*)bA)[lane];
    float2 bB2 = ((const float2*)bB)[lane];
    float2 o;
    o.x = 0.5f * (a0 + bA2.x + c0 + bB2.x);
    o.y = 0.5f * (a1 + bA2.y + c1 + bB2.y);
    ((float2*)(out + (size_t)warp * 64))[lane] = o;
    if (compute_alpha) {
        float2 v6 = ((const float2*)g_v[6])[lane];
        float p = o.x * v6.x + o.y * v6.y;
        #pragma unroll
        for (int d = 16; d; d >>= 1) p += __shfl_xor_sync(0xffffffffu, p, d);
        if (lane == 0) g_alpha[6][warp] = p;
    }
}

// ---------------- launch ------------------------------------------------------
extern "C" void kernel_launch(void* const* d_in, const int* in_sizes, int n_in,
                              void* d_out, int out_size)
{
    const float* x_target   = (const float*)d_in[0];
    const float* x_drug     = (const float*)d_in[1];
    const int*   ei_tt      = (const int*)d_in[2];
    const int*   ei_dt      = (const int*)d_in[3];
    const int*   ei_dd      = (const int*)d_in[4];
    const int*   ei_td      = (const int*)d_in[5];
    const float* W_tt       = (const float*)d_in[6];
    const float* att_tt_src = (const float*)d_in[7];
    const float* att_tt_dst = (const float*)d_in[8];
    const float* b_tt       = (const float*)d_in[9];
    const float* W_dt_src   = (const float*)d_in[10];
    const float* W_dt_dst   = (const float*)d_in[11];
    const float* att_dt_src = (const float*)d_in[12];
    const float* att_dt_dst = (const float*)d_in[13];
    const float* b_dt       = (const float*)d_in[14];
    const float* W_dd       = (const float*)d_in[15];
    const float* att_dd_src = (const float*)d_in[16];
    const float* att_dd_dst = (const float*)d_in[17];
    const float* b_dd       = (const float*)d_in[18];
    const float* W_td_src   = (const float*)d_in[19];
    const float* W_td_dst   = (const float*)d_in[20];
    const float* att_td_src = (const float*)d_in[21];
    const float* att_td_dst = (const float*)d_in[22];
    const float* b_td       = (const float*)d_in[23];

    float* out_t = (float*)d_out;
    float* out_d = out_t + (size_t)NT * 64;

    // zero counts + v = W@a + W^T halves
    init_kernel<<<NB + 12, 256>>>(W_tt, W_dt_src, W_dt_dst, W_dd, W_td_src, W_td_dst,
                                  att_tt_src, att_tt_dst, att_dt_src, att_dt_dst,
                                  att_dd_src, att_dd_dst, att_td_src, att_td_dst);

    // fused histogram x4 + alpha mat-vecs
    prep_kernel<<<4 * EB + 2 * AB, 256>>>(x_target, x_drug,
                                          ei_tt + NE, ei_dt + NE,
                                          ei_dd + NE, ei_td + NE);

    // CSR offsets (off_kernel also primes cursors)
    bsum_kernel<<<dim3(NB, 4), 256>>>();
    bscan_kernel<<<1, 256>>>();
    off_kernel<<<dim3(NB, 4), 256>>>();

    // bucket all 4 relations (src-only payload, cursor returns position)
    scatter4_kernel<<<4 * EB, 256>>>(ei_tt, ei_dt, ei_dd, ei_td);

    // src-feature GEMMs on tensor cores (mma.sync fp16, fp32 accum)
    hmma_gemm<128, 3><<<3 * GBK, 256>>>(x_target, x_drug, 0);

    // x_target_new = 0.5*(gat_tt + gat_dt), fused alpha6 = out . v6
    agg2_kernel<<<AB, 256>>>(0, 0, 1, b_tt, 1, 2, 3, b_dt, out_t, NT, 1);

    // td relation depends on x_target_new
    hmma_gemm<64, 1><<<GBK, 256>>>(out_t, out_t, 3);

    // x_drug_new = 0.5*(gat_dd + gat_td)
    agg2_kernel<<<AB, 256>>>(2, 4, 5, b_dd, 3, 6, 7, b_td, out_d, NT, 0);
}

// round 8
// speedup vs baseline: 1.4846x; 1.0254x over previous
#include <cuda_runtime.h>
#include <cuda_fp16.h>
#include <cstdint>

#define NT  50000
#define NE  800000
#define NEG_SLOPE 0.2f
#define NB  196        // ceil(50000/256)
#define GBK 391        // ceil(50000/128) gemm row tiles
#define AB  6250       // warp-per-node blocks (8 nodes/block)
#define EB  3125       // ceil(800000/256) edge blocks

// ---------------- scratch (static device globals) ---------------------------
__device__ __align__(16) __half g_H[4][(size_t)NT * 64]; // relation src features
__device__ __align__(16) __half g_Wh[4][64 * 128];       // W^T as half, [n][k]
__device__ float  g_alpha[8][NT];
__device__ float  g_v[8][128];
__device__ int    g_edges[4][NE];           // src index per bucketed edge
__device__ int    g_cnt[4][NT];             // counts, then reused as cursors
__device__ int    g_off[4][NT + 1];
__device__ int    g_bsum[4][NB];
__device__ int    g_boff[4][NB];

// ---------------- mma helpers -------------------------------------------------
__device__ __forceinline__ uint32_t smem_u32(const void* p) {
    uint32_t a;
    asm("{ .reg .u64 t; cvta.to.shared.u64 t, %1; cvt.u32.u64 %0, t; }"
        : "=r"(a) : "l"(p));
    return a;
}
__device__ __forceinline__ void ldm_x4(uint32_t* r, uint32_t addr) {
    asm volatile("ldmatrix.sync.aligned.m8n8.x4.shared.b16 {%0,%1,%2,%3}, [%4];"
                 : "=r"(r[0]), "=r"(r[1]), "=r"(r[2]), "=r"(r[3]) : "r"(addr));
}
__device__ __forceinline__ void ldm_x2(uint32_t* r, uint32_t addr) {
    asm volatile("ldmatrix.sync.aligned.m8n8.x2.shared.b16 {%0,%1}, [%2];"
                 : "=r"(r[0]), "=r"(r[1]) : "r"(addr));
}
__device__ __forceinline__ void mma16816(float* c, const uint32_t* a, const uint32_t* b) {
    asm volatile(
        "mma.sync.aligned.m16n8k16.row.col.f32.f16.f16.f32 "
        "{%0,%1,%2,%3}, {%4,%5,%6,%7}, {%8,%9}, {%0,%1,%2,%3};"
        : "+f"(c[0]), "+f"(c[1]), "+f"(c[2]), "+f"(c[3])
        : "r"(a[0]), "r"(a[1]), "r"(a[2]), "r"(a[3]), "r"(b[0]), "r"(b[1]));
}

// ---------------- HMMA GEMM: H(half) = X[N,K](f32) @ W[K,64] -----------------
template <int K, int NMAT>
__global__ __launch_bounds__(256) void hmma_gemm(
    const float* __restrict__ Xt, const float* __restrict__ Xd, int w0)
{
    __shared__ __half sA[128][72];
    __shared__ __half sB[64][72];

    const int tid = threadIdx.x;
    const int wid = tid >> 5, lane = tid & 31;
    const int which = (NMAT == 1) ? 0 : (int)(blockIdx.x / GBK);
    const int tile  = (NMAT == 1) ? (int)blockIdx.x : (int)(blockIdx.x % GBK);
    const float* __restrict__ X = (NMAT == 1) ? Xt : (which == 0 ? Xt : Xd);
    const __half* __restrict__ Wh = g_Wh[w0 + which];
    __half* __restrict__ Hout = g_H[w0 + which];
    const int row0 = tile * 128;

    const int wr = wid & 3;
    const int wc = wid >> 2;

    float acc[2][4][4];
    #pragma unroll
    for (int mi = 0; mi < 2; mi++)
        #pragma unroll
        for (int ni = 0; ni < 4; ni++)
            #pragma unroll
            for (int j = 0; j < 4; j++) acc[mi][ni][j] = 0.f;

    #pragma unroll
    for (int kc = 0; kc < K; kc += 64) {
        #pragma unroll
        for (int it = 0; it < 8; it++) {
            int idx = tid + it * 256;
            int r = idx >> 4, q = (idx & 15) * 4;
            int gr = row0 + r;
            float4 xv = make_float4(0.f, 0.f, 0.f, 0.f);
            if (gr < NT) xv = *(const float4*)(X + (size_t)gr * K + kc + q);
            *(__half2*)&sA[r][q]     = __floats2half2_rn(xv.x, xv.y);
            *(__half2*)&sA[r][q + 2] = __floats2half2_rn(xv.z, xv.w);
        }
        #pragma unroll
        for (int it = 0; it < 2; it++) {
            int idx = tid + it * 256;
            int r = idx >> 3, o = (idx & 7) * 8;
            uint4 v = *(const uint4*)(Wh + (size_t)r * K + kc + o);
            *(uint4*)&sB[r][o] = v;
        }
        __syncthreads();

        #pragma unroll
        for (int ks = 0; ks < 4; ks++) {
            int k0 = ks * 16;
            uint32_t af[2][4], bf[4][2];
            #pragma unroll
            for (int mi = 0; mi < 2; mi++) {
                uint32_t addr = smem_u32(&sA[wr * 32 + mi * 16 + (lane & 15)]
                                            [k0 + (lane >> 4) * 8]);
                ldm_x4(af[mi], addr);
            }
            #pragma unroll
            for (int ni = 0; ni < 4; ni++) {
                uint32_t addr = smem_u32(&sB[wc * 32 + ni * 8 + (lane & 7)]
                                            [k0 + ((lane >> 3) & 1) * 8]);
                ldm_x2(bf[ni], addr);
            }
            #pragma unroll
            for (int mi = 0; mi < 2; mi++)
                #pragma unroll
                for (int ni = 0; ni < 4; ni++)
                    mma16816(acc[mi][ni], af[mi], bf[ni]);
        }
        __syncthreads();
    }

    const int g = lane >> 2, tg = lane & 3;
    #pragma unroll
    for (int mi = 0; mi < 2; mi++) {
        #pragma unroll
        for (int half_ = 0; half_ < 2; half_++) {
            int gr = row0 + wr * 32 + mi * 16 + g + half_ * 8;
            if (gr < NT) {
                __half2* dst = (__half2*)(Hout + (size_t)gr * 64 + wc * 32);
                #pragma unroll
                for (int ni = 0; ni < 4; ni++) {
                    float c0 = acc[mi][ni][half_ * 2];
                    float c1 = acc[mi][ni][half_ * 2 + 1];
                    dst[ni * 4 + tg] = __floats2half2_rn(c0, c1);
                }
            }
        }
    }
}

// ---------------- K1: zero counts + v = W @ a + W^T half ---------------------
__global__ __launch_bounds__(256) void init_kernel(
    const float* W_tt, const float* W_dts, const float* W_dtd,
    const float* W_dd, const float* W_tds, const float* W_tdd,
    const float* a_tts, const float* a_ttd, const float* a_dts, const float* a_dtd,
    const float* a_dds, const float* a_ddd, const float* a_tds, const float* a_tdd)
{
    int b = blockIdx.x;
    if (b < NB) {
        int i = b * 256 + threadIdx.x;
        if (i < 50000) ((int4*)g_cnt)[i] = make_int4(0, 0, 0, 0);
        return;
    }
    if (b < NB + 4) {
        int j = b - NB;
        const float* W = (j == 0) ? W_tt : (j == 1) ? W_dts : (j == 2) ? W_dd : W_tds;
        int K = (j == 3) ? 64 : 128;
        for (int i = threadIdx.x; i < 64 * K; i += 256) {
            int n = i / K, k = i % K;
            g_Wh[j][i] = __float2half(W[k * 64 + n]);
        }
        return;
    }
    int j = b - NB - 4;
    const float* W = nullptr; const float* a = nullptr; int K = 128;
    switch (j) {
        case 0: W = W_tt;  a = a_tts; break;
        case 1: W = W_tt;  a = a_ttd; break;
        case 2: W = W_dts; a = a_dts; break;
        case 3: W = W_dtd; a = a_dtd; break;
        case 4: W = W_dd;  a = a_dds; break;
        case 5: W = W_dd;  a = a_ddd; break;
        case 6: W = W_tds; a = a_tds; K = 64; break;
        case 7: W = W_tdd; a = a_tdd; break;
    }
    int k = threadIdx.x;
    if (k < K) {
        float s = 0.f;
        #pragma unroll
        for (int c = 0; c < 64; c++) s += W[k * 64 + c] * a[c];
        g_v[j][k] = s;
    }
}

// ---------------- fused hist(4 rel) + alpha(target, drug) --------------------
__device__ __forceinline__ void alpha_node(const float* __restrict__ X, int node,
                                           int lane, const int* vis, int nv)
{
    const float* xr = X + (size_t)node * 128;
    float xv[4];
    #pragma unroll
    for (int t = 0; t < 4; t++) xv[t] = xr[lane + 32 * t];
    #pragma unroll 4
    for (int j = 0; j < nv; j++) {
        const float* v = g_v[vis[j]];
        float p = 0.f;
        #pragma unroll
        for (int t = 0; t < 4; t++) p += xv[t] * v[lane + 32 * t];
        #pragma unroll
        for (int d = 16; d; d >>= 1) p += __shfl_xor_sync(0xffffffffu, p, d);
        if (lane == 0) g_alpha[vis[j]][node] = p;
    }
}

__global__ __launch_bounds__(256) void prep_kernel(
    const float* __restrict__ xt, const float* __restrict__ xd,
    const int* __restrict__ d0, const int* __restrict__ d1,
    const int* __restrict__ d2, const int* __restrict__ d3)
{
    int b = blockIdx.x;
    if (b < 4 * EB) {
        int rel = b / EB;
        int i = (b % EB) * 256 + threadIdx.x;
        const int* d = (rel == 0) ? d0 : (rel == 1) ? d1 : (rel == 2) ? d2 : d3;
        if (i < NE) atomicAdd(&g_cnt[rel][d[i]], 1);
        return;
    }
    b -= 4 * EB;
    int wid = threadIdx.x >> 5, lane = threadIdx.x & 31;
    if (b < AB) {
        int node = b * 8 + wid;
        if (node >= NT) return;
        const int vis[3] = {0, 1, 3};
        alpha_node(xt, node, lane, vis, 3);
    } else {
        int node = (b - AB) * 8 + wid;
        if (node >= NT) return;
        const int vis[4] = {2, 4, 5, 7};
        alpha_node(xd, node, lane, vis, 4);
    }
}

// ---------------- 3-phase scan ------------------------------------------------
__global__ void bsum_kernel() {
    int rel = blockIdx.y;
    int idx = blockIdx.x * 256 + threadIdx.x;
    int v = (idx < NT) ? g_cnt[rel][idx] : 0;
    #pragma unroll
    for (int d = 16; d; d >>= 1) v += __shfl_xor_sync(0xffffffffu, v, d);
    __shared__ int s[8];
    int lane = threadIdx.x & 31, wid = threadIdx.x >> 5;
    if (lane == 0) s[wid] = v;
    __syncthreads();
    if (threadIdx.x == 0) {
        int t = 0;
        #pragma unroll
        for (int i = 0; i < 8; i++) t += s[i];
        g_bsum[rel][blockIdx.x] = t;
    }
}

// 1 warp per relation, contiguous 7-element chunks per lane
__global__ void bscan_kernel() {
    int wid = threadIdx.x >> 5, lane = threadIdx.x & 31;
    if (wid >= 4) return;
    const int per = 7;                // 32*7 = 224 >= NB
    int base = lane * per;
    int v[7];
    int tot = 0;
    #pragma unroll
    for (int j = 0; j < per; j++) {
        int idx = base + j;
        v[j] = (idx < NB) ? g_bsum[wid][idx] : 0;
        tot += v[j];
    }
    int x = tot;
    #pragma unroll
    for (int d = 1; d < 32; d <<= 1) {
        int y = __shfl_up_sync(0xffffffffu, x, d);
        if (lane >= d) x += y;
    }
    int run = x - tot;                // exclusive prefix of lane totals
    #pragma unroll
    for (int j = 0; j < per; j++) {
        int idx = base + j;
        if (idx < NB) g_boff[wid][idx] = run;
        run += v[j];
    }
}

// writes offsets; converts g_cnt into ready-to-use cursors (cursor = excl offset)
__global__ void off_kernel() {
    int rel = blockIdx.y;
    int idx = blockIdx.x * 256 + threadIdx.x;
    int v = (idx < NT) ? g_cnt[rel][idx] : 0;
    __shared__ int wsum[8];
    int lane = threadIdx.x & 31, wid = threadIdx.x >> 5;
    int x = v;
    #pragma unroll
    for (int d = 1; d < 32; d <<= 1) {
        int y = __shfl_up_sync(0xffffffffu, x, d);
        if (lane >= d) x += y;
    }
    if (lane == 31) wsum[wid] = x;
    __syncthreads();
    if (wid == 0) {
        int sv = (lane < 8) ? wsum[lane] : 0;
        #pragma unroll
        for (int d = 1; d < 8; d <<= 1) {
            int y = __shfl_up_sync(0xffffffffu, sv, d);
            if (lane >= d) sv += y;
        }
        if (lane < 8) wsum[lane] = sv;
    }
    __syncthreads();
    int incl = x + (wid ? wsum[wid - 1] : 0) + g_boff[rel][blockIdx.x];
    if (idx < NT) {
        g_off[rel][idx + 1] = incl;
        g_cnt[rel][idx] = incl - v;
    }
    if (idx == 0) g_off[rel][0] = 0;
}

// ---------------- scatter: all 4 relations, src-only payload ------------------
__global__ void scatter4_kernel(const int* __restrict__ e0, const int* __restrict__ e1,
                                const int* __restrict__ e2, const int* __restrict__ e3)
{
    int rel = blockIdx.x / EB;
    int i = (blockIdx.x % EB) * 256 + threadIdx.x;
    if (i >= NE) return;
    const int* e = (rel == 0) ? e0 : (rel == 1) ? e1 : (rel == 2) ? e2 : e3;
    int s = e[i], d = e[i + NE];
    int pos = atomicAdd(&g_cnt[rel][d], 1);
    g_edges[rel][pos] = s;
}

// ---------------- per-node GAT aggregation (logit+softmax in-place) -----------
__device__ __forceinline__ void gat_node(int rel, int asIdx, float ad,
                                         int node, int lane, float& o0, float& o1)
{
    const int* __restrict__ E = g_edges[rel];
    const __half2* __restrict__ H = (const __half2*)g_H[rel];
    const float* __restrict__ As = g_alpha[asIdx];
    int s = g_off[rel][node], e = g_off[rel][node + 1];
    float den = 0.f, a0 = 0.f, a1 = 0.f;
    int i = s;
    for (; i + 4 <= e; i += 4) {
        int s0 = E[i], s1 = E[i + 1], s2 = E[i + 2], s3 = E[i + 3];
        float l0 = As[s0] + ad, l1 = As[s1] + ad;
        float l2 = As[s2] + ad, l3 = As[s3] + ad;
        float2 f0 = __half22float2(H[(size_t)s0 * 32 + lane]);
        float2 f1 = __half22float2(H[(size_t)s1 * 32 + lane]);
        float2 f2 = __half22float2(H[(size_t)s2 * 32 + lane]);
        float2 f3 = __half22float2(H[(size_t)s3 * 32 + lane]);
        l0 = (l0 > 0.f) ? l0 : NEG_SLOPE * l0;
        l1 = (l1 > 0.f) ? l1 : NEG_SLOPE * l1;
        l2 = (l2 > 0.f) ? l2 : NEG_SLOPE * l2;
        l3 = (l3 > 0.f) ? l3 : NEG_SLOPE * l3;
        float w0 = __expf(l0), w1 = __expf(l1), w2 = __expf(l2), w3 = __expf(l3);
        den += (w0 + w1) + (w2 + w3);
        a0 += w0 * f0.x + w1 * f1.x + w2 * f2.x + w3 * f3.x;
        a1 += w0 * f0.y + w1 * f1.y + w2 * f2.y + w3 * f3.y;
    }
    for (; i < e; i++) {
        int s0 = E[i];
        float l0 = As[s0] + ad;
        float2 f0 = __half22float2(H[(size_t)s0 * 32 + lane]);
        l0 = (l0 > 0.f) ? l0 : NEG_SLOPE * l0;
        float w0 = __expf(l0);
        den += w0;
        a0 += w0 * f0.x;
        a1 += w0 * f0.y;
    }
    float inv = 1.f / (den + 1e-16f);
    o0 = a0 * inv;
    o1 = a1 * inv;
}

// target: out = 0.5*((gat0 + b_tt) + (gat1 + b_dt)), fused alpha6 = out.v6
__global__ __launch_bounds__(256) void agg_t_kernel(
    const float* __restrict__ bA, const float* __restrict__ bB,
    float* __restrict__ out)
{
    int warp = (blockIdx.x * blockDim.x + threadIdx.x) >> 5;
    int lane = threadIdx.x & 31;
    if (warp >= NT) return;
    float adA = g_alpha[1][warp], adB = g_alpha[3][warp];
    float a0, a1, c0, c1;
    gat_node(0, 0, adA, warp, lane, a0, a1);
    gat_node(1, 2, adB, warp, lane, c0, c1);
    float2 bA2 = ((const float2*)bA)[lane];
    float2 bB2 = ((const float2*)bB)[lane];
    float2 o;
    o.x = 0.5f * (a0 + bA2.x + c0 + bB2.x);
    o.y = 0.5f * (a1 + bA2.y + c1 + bB2.y);
    ((float2*)(out + (size_t)warp * 64))[lane] = o;
    float2 v6 = ((const float2*)g_v[6])[lane];
    float p = o.x * v6.x + o.y * v6.y;
    #pragma unroll
    for (int d = 16; d; d >>= 1) p += __shfl_xor_sync(0xffffffffu, p, d);
    if (lane == 0) g_alpha[6][warp] = p;
}

// drug dd partial: out_d = gat_dd + b_dd (unscaled)
__global__ __launch_bounds__(256) void agg_dd_kernel(
    const float* __restrict__ bA, float* __restrict__ out)
{
    int warp = (blockIdx.x * blockDim.x + threadIdx.x) >> 5;
    int lane = threadIdx.x & 31;
    if (warp >= NT) return;
    float ad = g_alpha[5][warp];
    float a0, a1;
    gat_node(2, 4, ad, warp, lane, a0, a1);
    float2 b2 = ((const float2*)bA)[lane];
    float2 o;
    o.x = a0 + b2.x;
    o.y = a1 + b2.y;
    ((float2*)(out + (size_t)warp * 64))[lane] = o;
}

// drug final: out_d = 0.5*(partial + gat_td + b_td)
__global__ __launch_bounds__(256) void agg_td_kernel(
    const float* __restrict__ bB, float* __restrict__ out)
{
    int warp = (blockIdx.x * blockDim.x + threadIdx.x) >> 5;
    int lane = threadIdx.x & 31;
    if (warp >= NT) return;
    float ad = g_alpha[7][warp];
    float a0, a1;
    gat_node(3, 6, ad, warp, lane, a0, a1);
    float2 b2 = ((const float2*)bB)[lane];
    float2* orow = (float2*)(out + (size_t)warp * 64);
    float2 p = orow[lane];
    p.x = 0.5f * (p.x + a0 + b2.x);
    p.y = 0.5f * (p.y + a1 + b2.y);
    orow[lane] = p;
}

// ---------------- launch ------------------------------------------------------
extern "C" void kernel_launch(void* const* d_in, const int* in_sizes, int n_in,
                              void* d_out, int out_size)
{
    const float* x_target   = (const float*)d_in[0];
    const float* x_drug     = (const float*)d_in[1];
    const int*   ei_tt      = (const int*)d_in[2];
    const int*   ei_dt      = (const int*)d_in[3];
    const int*   ei_dd      = (const int*)d_in[4];
    const int*   ei_td      = (const int*)d_in[5];
    const float* W_tt       = (const float*)d_in[6];
    const float* att_tt_src = (const float*)d_in[7];
    const float* att_tt_dst = (const float*)d_in[8];
    const float* b_tt       = (const float*)d_in[9];
    const float* W_dt_src   = (const float*)d_in[10];
    const float* W_dt_dst   = (const float*)d_in[11];
    const float* att_dt_src = (const float*)d_in[12];
    const float* att_dt_dst = (const float*)d_in[13];
    const float* b_dt       = (const float*)d_in[14];
    const float* W_dd       = (const float*)d_in[15];
    const float* att_dd_src = (const float*)d_in[16];
    const float* att_dd_dst = (const float*)d_in[17];
    const float* b_dd       = (const float*)d_in[18];
    const float* W_td_src   = (const float*)d_in[19];
    const float* W_td_dst   = (const float*)d_in[20];
    const float* att_td_src = (const float*)d_in[21];
    const float* att_td_dst = (const float*)d_in[22];
    const float* b_td       = (const float*)d_in[23];

    float* out_t = (float*)d_out;
    float* out_d = out_t + (size_t)NT * 64;

    // side stream + events for graph fork/join (created fresh each call;
    // creation is a host-side op, legal inside stream capture)
    cudaStream_t side;
    cudaStreamCreateWithFlags(&side, cudaStreamNonBlocking);
    cudaEvent_t evFork, evGemm, evScat, evDD;
    cudaEventCreateWithFlags(&evFork, cudaEventDisableTiming);
    cudaEventCreateWithFlags(&evGemm, cudaEventDisableTiming);
    cudaEventCreateWithFlags(&evScat, cudaEventDisableTiming);
    cudaEventCreateWithFlags(&evDD,   cudaEventDisableTiming);

    // main: zero counts + v = W@a + W^T halves
    init_kernel<<<NB + 12, 256>>>(W_tt, W_dt_src, W_dt_dst, W_dd, W_td_src, W_td_dst,
                                  att_tt_src, att_tt_dst, att_dt_src, att_dt_dst,
                                  att_dd_src, att_dd_dst, att_td_src, att_td_dst);
    cudaEventRecord(evFork, 0);

    // side: the 3 big GEMMs overlap the CSR chain
    cudaStreamWaitEvent(side, evFork, 0);
    hmma_gemm<128, 3><<<3 * GBK, 256, 0, side>>>(x_target, x_drug, 0);
    cudaEventRecord(evGemm, side);

    // main: fused histogram x4 + alpha mat-vecs
    prep_kernel<<<4 * EB + 2 * AB, 256>>>(x_target, x_drug,
                                          ei_tt + NE, ei_dt + NE,
                                          ei_dd + NE, ei_td + NE);

    // main: CSR offsets
    bsum_kernel<<<dim3(NB, 4), 256>>>();
    bscan_kernel<<<1, 128>>>();
    off_kernel<<<dim3(NB, 4), 256>>>();

    // main: bucket all 4 relations
    scatter4_kernel<<<4 * EB, 256>>>(ei_tt, ei_dt, ei_dd, ei_td);
    cudaEventRecord(evScat, 0);

    // side: dd aggregation (needs gemm [same stream] + scatter)
    cudaStreamWaitEvent(side, evScat, 0);
    agg_dd_kernel<<<AB, 256, 0, side>>>(b_dd, out_d);
    cudaEventRecord(evDD, side);

    // main: target aggregation (needs gemm + scatter)
    cudaStreamWaitEvent(0, evGemm, 0);
    agg_t_kernel<<<AB, 256>>>(b_tt, b_dt, out_t);

    // main: td gemm on x_target_new
    hmma_gemm<64, 1><<<GBK, 256>>>(out_t, out_t, 3);

    // main: final drug combine (needs dd partial)
    cudaStreamWaitEvent(0, evDD, 0);
    agg_td_kernel<<<AB, 256>>>(b_td, out_d);
}